// round 11
// baseline (speedup 1.0000x reference)
#include <cuda_runtime.h>
#include <cuda_bf16.h>
#include <cstdint>

// Problem constants
#define Bx     4
#define Nn     1024
#define DIM    1024
#define HEADS  16
#define DH     64
#define INNER  1024
#define PROJ_H 16
#define TOP_K  256
#define SCALE  0.125f
#define LN_EPS 1e-5f

#define M_TOK  (Bx * Nn)          // 4096 tokens
#define BH     (Bx * HEADS)       // 64
#define GBK    16

// ---------------- scratch (device globals; no allocation allowed) -----------
__device__ float gWqm[DH * DIM];                 // (1/16) sum_h w_q rows
__device__ float gScores[Bx * Nn];
__device__ float gGate[Bx * Nn];
__device__ float gAttnOut[Bx * Nn * INNER];      // active rows only

__device__ int   gActIdx[Bx * TOP_K];
__device__ int   gActCount[Bx];
__device__ float gGateC[Bx * TOP_K];
__device__ float gQc[BH * TOP_K * DH];           // compact Q (active only)
__device__ float gKc[BH * TOP_K * DH];           // compact K
__device__ float gVc[BH * TOP_K * DH];           // compact V
__device__ float gXsumP[8 * Bx * DIM];           // partial x sums
__device__ float gXsum[Bx * DIM];                // per-batch sum of x rows
__device__ float gVsumAll[BH * DH];              // = Wv . xsum
__device__ float gInactRow[Bx * DIM];

// ============ K_A: wqmean (blocks 0..255) + xsum_part (256..383) ============
__global__ __launch_bounds__(256)
void kA_prep(const float* __restrict__ Wqkv, const float* __restrict__ x)
{
    const int blk = blockIdx.x;
    const int tid = threadIdx.x;
    if (blk < 256) {
        const int idx = blk * 256 + tid;
        const int d = idx >> 10, k = idx & 1023;
        float s = 0.f;
#pragma unroll
        for (int h = 0; h < HEADS; h++)
            s += Wqkv[(size_t)(h * DH + d) * DIM + k];
        gWqm[(size_t)d * DIM + k] = s * (1.0f / 16.0f);
    } else {
        const int e = blk - 256;                 // 0..127
        const int kb = e & 3, b = (e >> 2) & 3, sl = e >> 4;
        const int k = kb * 256 + tid;
        float s = 0.f;
        const float* p = x + ((size_t)b * Nn + sl * 128) * DIM + k;
#pragma unroll 8
        for (int n = 0; n < 128; n++) s += p[(size_t)n * DIM];
        gXsumP[((size_t)sl * Bx + b) * DIM + k] = s;
    }
}

// ===== K_B: qmean GEMM + fused gate epilogue (0..63) + xsum_reduce (64..79) =
__global__ __launch_bounds__(256)
void kB_qmean_gate(const float* __restrict__ A,
                   const float* __restrict__ ln_g, const float* __restrict__ ln_b,
                   const float* __restrict__ w1, const float* __restrict__ b1,
                   const float* __restrict__ w2, const float* __restrict__ b2)
{
    const int blk = blockIdx.x;
    const int tid = threadIdx.x;

    if (blk >= 64) {                              // xsum_reduce
        const int e = blk - 64;                   // 0..15
        const int b = e >> 2;
        const int k = (e & 3) * 256 + tid;
        float s = 0.f;
#pragma unroll
        for (int sl = 0; sl < 8; sl++) s += gXsumP[((size_t)sl * Bx + b) * DIM + k];
        gXsum[b * DIM + k] = s;
        return;
    }

    // qmean 64x64 tile: m0 = blk*64, N = 64 (full)
    __shared__ float As[GBK][64 + 4];
    __shared__ float Bs[GBK][64 + 4];
    __shared__ float Qs[64][65];

    const int ty = tid >> 4;
    const int tx = tid & 15;
    const int m0 = blk * 64;
    const int lr = tid >> 2;
    const int lc = (tid & 3) * 4;

    float acc[4][4];
#pragma unroll
    for (int i = 0; i < 4; i++)
#pragma unroll
        for (int j = 0; j < 4; j++) acc[i][j] = 0.f;

    for (int k0 = 0; k0 < DIM; k0 += GBK) {
        float4 av = *(const float4*)(A + (size_t)(m0 + lr) * DIM + k0 + lc);
        float4 bv = *(const float4*)(gWqm + (size_t)lr * DIM + k0 + lc);
        As[lc + 0][lr] = av.x; As[lc + 1][lr] = av.y;
        As[lc + 2][lr] = av.z; As[lc + 3][lr] = av.w;
        Bs[lc + 0][lr] = bv.x; Bs[lc + 1][lr] = bv.y;
        Bs[lc + 2][lr] = bv.z; Bs[lc + 3][lr] = bv.w;
        __syncthreads();
#pragma unroll
        for (int kk = 0; kk < GBK; kk++) {
            float4 a = *(const float4*)&As[kk][ty * 4];
            float4 b = *(const float4*)&Bs[kk][tx * 4];
            float ar[4] = {a.x, a.y, a.z, a.w};
            float br[4] = {b.x, b.y, b.z, b.w};
#pragma unroll
            for (int i = 0; i < 4; i++)
#pragma unroll
                for (int j = 0; j < 4; j++) acc[i][j] += ar[i] * br[j];
        }
        __syncthreads();
    }

#pragma unroll
    for (int i = 0; i < 4; i++)
#pragma unroll
        for (int j = 0; j < 4; j++)
            Qs[ty * 4 + i][tx * 4 + j] = acc[i][j];
    __syncthreads();

    // fused gate: thread t < 64 handles token m0+t
    if (tid < 64) {
        const int t = tid;
        float mu = 0.f, sq = 0.f;
#pragma unroll
        for (int e = 0; e < 64; e++) { float v = Qs[t][e]; mu += v; sq += v * v; }
        mu *= (1.0f / 64.0f);
        const float var = sq * (1.0f / 64.0f) - mu * mu;
        const float rs = rsqrtf(var + LN_EPS);
#pragma unroll
        for (int e = 0; e < 64; e++)
            Qs[t][e] = (Qs[t][e] - mu) * rs * ln_g[e] + ln_b[e];
        float sc = b2[0];
#pragma unroll
        for (int p = 0; p < PROJ_H; p++) {
            float a = b1[p];
#pragma unroll
            for (int e = 0; e < 64; e++) a += Qs[t][e] * w1[p * DH + e];
            float g = 0.5f * a * (1.0f + erff(a * 0.70710678118654752f));
            sc += g * w2[p];
        }
        gScores[m0 + t] = sc;
    }
}

// ====== K_C: radix-select topk (blocks 0..3) + vsumall (blocks 4..1027) =====
__global__ __launch_bounds__(512)
void kC_topk_vsum(const float* __restrict__ Wqkv)
{
    const int blk = blockIdx.x;
    const int tid = threadIdx.x;

    if (blk >= 4) {                               // vsumall: hd = blk-4
        const int hd = blk - 4;
        __shared__ float red[Bx][256];
        const float4* wrow = (const float4*)(Wqkv + (size_t)(2 * INNER + hd) * DIM);
        if (tid < 256) {
            float4 w = wrow[tid];
#pragma unroll
            for (int b = 0; b < Bx; b++) {
                float4 v = ((const float4*)(gXsum + b * DIM))[tid];
                red[b][tid] = w.x * v.x + w.y * v.y + w.z * v.z + w.w * v.w;
            }
        }
        __syncthreads();
        for (int off = 128; off > 0; off >>= 1) {
            if (tid < off)
#pragma unroll
                for (int b = 0; b < Bx; b++) red[b][tid] += red[b][tid + off];
            __syncthreads();
        }
        if (tid < Bx) gVsumAll[tid * 1024 + hd] = red[tid][0];
        return;
    }

    // top-k via 4-pass MSD radix select (exact k-th largest)
    const int b = blk;
    __shared__ uint32_t keys[Nn];
    __shared__ uint32_t hist[256];
    __shared__ uint32_t sPrefix;
    __shared__ int sNeed, cnt;

    for (int t = tid; t < Nn; t += 512) {
        uint32_t u = __float_as_uint(gScores[b * Nn + t]);
        keys[t] = (u & 0x80000000u) ? ~u : (u | 0x80000000u);
    }
    if (tid == 0) { sPrefix = 0; sNeed = TOP_K; cnt = 0; }
    __syncthreads();

#pragma unroll
    for (int shift = 24; shift >= 0; shift -= 8) {
        if (tid < 256) hist[tid] = 0;
        __syncthreads();
        const uint32_t pref = sPrefix;
        for (int t = tid; t < Nn; t += 512) {
            uint32_t u = keys[t];
            bool match = (shift == 24) || ((u >> (shift + 8)) == pref);
            if (match) atomicAdd(&hist[(u >> shift) & 255u], 1u);
        }
        __syncthreads();
        if (tid == 0) {
            int acc = 0, k = sNeed;
            for (int bin = 255; bin >= 0; bin--) {
                int c = (int)hist[bin];
                if (acc + c >= k) {
                    sPrefix = (pref << 8) | (uint32_t)bin;
                    sNeed = k - acc;
                    break;
                }
                acc += c;
            }
        }
        __syncthreads();
    }

    const uint32_t Tu = sPrefix;
    const float thresh = (Tu & 0x80000000u) ? __uint_as_float(Tu & 0x7FFFFFFFu)
                                            : __uint_as_float(~Tu);

    for (int t = tid; t < Nn; t += 512) {
        float sc = gScores[b * Nn + t];
        float g = 0.0f;
        if (sc >= thresh) {
            int pos = atomicAdd(&cnt, 1);
            if (pos < TOP_K) {
                g = 1.0f / (1.0f + expf(-sc));
                gActIdx[b * TOP_K + pos] = t;
                gGateC[b * TOP_K + pos] = g;
            }
        }
        gGate[b * Nn + t] = g;
    }
    __syncthreads();
    if (tid == 0) gActCount[b] = (cnt < TOP_K) ? cnt : TOP_K;
}

// ======= K_D: qkv_active GEMM (blocks 0..383) + inact_row (384..399) ========
__global__ __launch_bounds__(256)
void kD_qkv_inrow(const float* __restrict__ A, const float* __restrict__ Wqkv,
                  const float* __restrict__ Wout, const float* __restrict__ bias)
{
    const int blk = blockIdx.x;
    const int tid = threadIdx.x;

    if (blk >= 384) {                             // inact_row
        const int e = blk - 384;                  // 0..15
        const int b = e >> 2;
        const int n = (e & 3) * 256 + tid;
        const float invN = 1.0f / (float)Nn;
        const float4* vrow = (const float4*)(gVsumAll + b * INNER);
        const float4* wrow = (const float4*)(Wout + (size_t)n * INNER);
        float s = 0.f;
#pragma unroll 8
        for (int c = 0; c < INNER / 4; c++) {
            float4 v = vrow[c];
            float4 w = wrow[c];
            s += v.x * w.x + v.y * w.y + v.z * w.z + v.w * w.w;
        }
        gInactRow[b * DIM + n] = s * invN + bias[n];
        return;
    }

    // qkv_active: 128x64 tile, 8x4 per thread
    __shared__ float As[GBK][128 + 4];
    __shared__ float Bs[GBK][64 + 4];
    __shared__ int   sidx[128];
    __shared__ int   slive[128];

    const int nb = blk % 48;
    const int yb = blk / 48;                      // 0..7
    const int b  = yb >> 1;
    const int mt = yb & 1;
    const int n0 = nb * 64;

    const int ty = tid >> 4;
    const int tx = tid & 15;
    const int alr = tid >> 1;
    const int alc = (tid & 1) * 8;
    const int blr = tid >> 2;
    const int blc = (tid & 3) * 4;

    const int cnt = gActCount[b];
    if (tid < 128) {
        const int ic = mt * 128 + tid;
        const bool lv = (ic < cnt);
        slive[tid] = lv;
        sidx[tid]  = lv ? gActIdx[b * TOP_K + ic] : gActIdx[b * TOP_K];
    }
    __syncthreads();

    const float* aptr = A + ((size_t)(b * Nn + sidx[alr])) * DIM + alc;
    const float* bptr = Wqkv + (size_t)(n0 + blr) * DIM + blc;

    float acc[8][4];
#pragma unroll
    for (int i = 0; i < 8; i++)
#pragma unroll
        for (int j = 0; j < 4; j++) acc[i][j] = 0.f;

    for (int k0 = 0; k0 < DIM; k0 += GBK) {
        float4 a0 = *(const float4*)(aptr + k0);
        float4 a1 = *(const float4*)(aptr + k0 + 4);
        float4 bv = *(const float4*)(bptr + k0);
#pragma unroll
        for (int i = 0; i < 4; i++) {
            As[alc + i][alr]     = ((const float*)&a0)[i];
            As[alc + 4 + i][alr] = ((const float*)&a1)[i];
            Bs[blc + i][blr]     = ((const float*)&bv)[i];
        }
        __syncthreads();
#pragma unroll
        for (int kk = 0; kk < GBK; kk++) {
            float4 x0 = *(const float4*)&As[kk][ty * 8];
            float4 x1 = *(const float4*)&As[kk][ty * 8 + 4];
            float4 y  = *(const float4*)&Bs[kk][tx * 4];
            float xr[8] = {x0.x, x0.y, x0.z, x0.w, x1.x, x1.y, x1.z, x1.w};
            float yr[4] = {y.x, y.y, y.z, y.w};
#pragma unroll
            for (int i = 0; i < 8; i++)
#pragma unroll
                for (int j = 0; j < 4; j++) acc[i][j] += xr[i] * yr[j];
        }
        __syncthreads();
    }

#pragma unroll
    for (int i = 0; i < 8; i++) {
        const int r = ty * 8 + i;
        if (slive[r]) {
            const int ic = mt * 128 + r;
#pragma unroll
            for (int j = 0; j < 4; j++) {
                const int n = n0 + tx * 4 + j;
                const int which = n >> 10;
                const int inner = n & 1023;
                const int h = inner >> 6, d = inner & 63;
                float* dst = (which == 0) ? gQc : (which == 1) ? gKc : gVc;
                dst[(((size_t)(b * HEADS + h)) * TOP_K + ic) * DH + d] = acc[i][j];
            }
        }
    }
}

// ============== K_F: attention for ACTIVE queries (VsumAll trick) ===========
#define AT_BJ 64

__global__ __launch_bounds__(128)
void attn_active_kernel()
{
    const int blk = blockIdx.x;
    const int bh = blk >> 1;
    const int half = blk & 1;
    const int b = bh >> 4;
    const int h = bh & 15;
    const int tid = threadIdx.x;
    const int ic = half * 128 + tid;

    const int cnt = gActCount[b];
    const bool live = (ic < cnt);
    const int i = live ? gActIdx[b * TOP_K + ic] : 0;

    __shared__ float4 ksm[AT_BJ][16];
    __shared__ float4 vsm[AT_BJ][16];
    __shared__ float  gsm[AT_BJ];

    float4 q[16];
    {
        const float4* qp = (const float4*)(gQc + ((size_t)bh * TOP_K + ic) * DH);
#pragma unroll
        for (int c = 0; c < 16; c++) q[c] = live ? qp[c] : make_float4(0.f, 0.f, 0.f, 0.f);
    }
    const float gi = live ? gGateC[b * TOP_K + ic] * SCALE : 0.f;

    // acc = sum_active (p-1)*Vc ; add VsumAll at the end (== VsumIn + sum p*Vc)
    float4 acc[16];
#pragma unroll
    for (int c = 0; c < 16; c++) acc[c] = make_float4(0.f, 0.f, 0.f, 0.f);
    float l = (float)(Nn - cnt);

    for (int j0 = 0; j0 < cnt; j0 += AT_BJ) {
        const int jn = min(AT_BJ, cnt - j0);
        __syncthreads();
        for (int t = tid; t < AT_BJ * 16; t += 128) {
            int j = t >> 4, c = t & 15;
            if (j < jn) {
                const size_t src = ((size_t)bh * TOP_K + j0 + j) * 16 + c;
                ksm[j][c] = ((const float4*)gKc)[src];
                vsm[j][c] = ((const float4*)gVc)[src];
            }
        }
        if (tid < AT_BJ && tid < jn) gsm[tid] = gGateC[b * TOP_K + j0 + tid];
        __syncthreads();

        for (int j = 0; j < jn; j++) {
            float s = 0.f;
#pragma unroll
            for (int c = 0; c < 16; c++) {
                float4 kv = ksm[j][c];
                s += q[c].x * kv.x + q[c].y * kv.y + q[c].z * kv.z + q[c].w * kv.w;
            }
            float p = __expf(s * gi * gsm[j]);
            l += p;
            const float pm1 = p - 1.0f;
#pragma unroll
            for (int c = 0; c < 16; c++) {
                float4 vv = vsm[j][c];
                acc[c].x += pm1 * vv.x; acc[c].y += pm1 * vv.y;
                acc[c].z += pm1 * vv.z; acc[c].w += pm1 * vv.w;
            }
        }
    }

    if (live) {
        const float inv = 1.0f / l;
        const float4* vall = (const float4*)(gVsumAll + bh * DH);
        float4* orow = (float4*)(gAttnOut + (((size_t)(b * Nn + i)) * HEADS + h) * DH);
#pragma unroll
        for (int c = 0; c < 16; c++) {
            float4 a = acc[c];
            float4 v = vall[c];
            a.x = (a.x + v.x) * inv; a.y = (a.y + v.y) * inv;
            a.z = (a.z + v.z) * inv; a.w = (a.w + v.w) * inv;
            orow[c] = a;
        }
    }
}

// ======= K_G: out_active GEMM (blocks 0..127) + inact_bcast (128..639) ======
__global__ __launch_bounds__(256)
void kG_out(const float* __restrict__ Bm, const float* __restrict__ bias,
            float* __restrict__ C)
{
    const int blk = blockIdx.x;
    const int tid = threadIdx.x;

    if (blk >= 128) {                             // bcast: 8 tokens per block
        const int e = blk - 128;                  // 0..511
        for (int s = 0; s < 8; s++) {
            const int token = e * 8 + s;
            if (gGate[token] != 0.0f) continue;
            const int b = token >> 10;
            ((float4*)(C + (size_t)token * DIM))[tid] =
                ((const float4*)(gInactRow + b * DIM))[tid];
        }
        return;
    }

    __shared__ float As[GBK][128 + 4];
    __shared__ float Bs[GBK][64 + 4];
    __shared__ int   sidx[128];
    __shared__ int   slive[128];

    const int nb = blk % 16;
    const int yb = blk / 16;                      // 0..7
    const int b  = yb >> 1;
    const int mt = yb & 1;
    const int n0 = nb * 64;

    const int ty = tid >> 4;
    const int tx = tid & 15;
    const int alr = tid >> 1;
    const int alc = (tid & 1) * 8;
    const int blr = tid >> 2;
    const int blc = (tid & 3) * 4;

    const int cnt = gActCount[b];
    if (tid < 128) {
        const int ic = mt * 128 + tid;
        const bool lv = (ic < cnt);
        slive[tid] = lv;
        sidx[tid]  = lv ? gActIdx[b * TOP_K + ic] : gActIdx[b * TOP_K];
    }
    __syncthreads();

    const float* aptr = gAttnOut + ((size_t)(b * Nn + sidx[alr])) * INNER + alc;
    const float* bptr = Bm + (size_t)(n0 + blr) * INNER + blc;

    float acc[8][4];
#pragma unroll
    for (int i = 0; i < 8; i++)
#pragma unroll
        for (int j = 0; j < 4; j++) acc[i][j] = 0.f;

    for (int k0 = 0; k0 < INNER; k0 += GBK) {
        float4 a0 = *(const float4*)(aptr + k0);
        float4 a1 = *(const float4*)(aptr + k0 + 4);
        float4 bv = *(const float4*)(bptr + k0);
#pragma unroll
        for (int i = 0; i < 4; i++) {
            As[alc + i][alr]     = ((const float*)&a0)[i];
            As[alc + 4 + i][alr] = ((const float*)&a1)[i];
            Bs[blc + i][blr]     = ((const float*)&bv)[i];
        }
        __syncthreads();
#pragma unroll
        for (int kk = 0; kk < GBK; kk++) {
            float4 x0 = *(const float4*)&As[kk][ty * 8];
            float4 x1 = *(const float4*)&As[kk][ty * 8 + 4];
            float4 y  = *(const float4*)&Bs[kk][tx * 4];
            float xr[8] = {x0.x, x0.y, x0.z, x0.w, x1.x, x1.y, x1.z, x1.w};
            float yr[4] = {y.x, y.y, y.z, y.w};
#pragma unroll
            for (int i = 0; i < 8; i++)
#pragma unroll
                for (int j = 0; j < 4; j++) acc[i][j] += xr[i] * yr[j];
        }
        __syncthreads();
    }

#pragma unroll
    for (int i = 0; i < 8; i++) {
        const int r = ty * 8 + i;
        if (slive[r]) {
            const int token = sidx[r];
#pragma unroll
            for (int j = 0; j < 4; j++) {
                const int n = n0 + tx * 4 + j;
                C[((size_t)(b * Nn + token)) * DIM + n] = acc[i][j] + bias[n];
            }
        }
    }
}

// ---------------- launch ----------------------------------------------------
extern "C" void kernel_launch(void* const* d_in, const int* in_sizes, int n_in,
                              void* d_out, int out_size)
{
    const float* x     = (const float*)d_in[0];
    const float* w_qkv = (const float*)d_in[1];
    const float* w_out = (const float*)d_in[2];
    const float* b_out = (const float*)d_in[3];
    const float* ln_g  = (const float*)d_in[4];
    const float* ln_b  = (const float*)d_in[5];
    const float* w1    = (const float*)d_in[6];
    const float* b1    = (const float*)d_in[7];
    const float* w2    = (const float*)d_in[8];
    const float* b2    = (const float*)d_in[9];
    float* out = (float*)d_out;

    kA_prep<<<384, 256>>>(w_qkv, x);                              // wqmean + xsum_part
    kB_qmean_gate<<<80, 256>>>(x, ln_g, ln_b, w1, b1, w2, b2);    // qmean+gate + xsum_reduce
    kC_topk_vsum<<<1028, 512>>>(w_qkv);                           // topk + vsumall
    kD_qkv_inrow<<<400, 256>>>(x, w_qkv, w_out, b_out);           // qkv_active + inact_row
    attn_active_kernel<<<BH * 2, 128>>>();
    kG_out<<<640, 256>>>(w_out, b_out, out);                      // out_active + bcast
}

// round 12
// speedup vs baseline: 1.5488x; 1.5488x over previous
#include <cuda_runtime.h>
#include <cuda_bf16.h>
#include <cstdint>

// Problem constants
#define Bx     4
#define Nn     1024
#define DIM    1024
#define HEADS  16
#define DH     64
#define INNER  1024
#define PROJ_H 16
#define TOP_K  256
#define SCALE  0.125f
#define LN_EPS 1e-5f

#define M_TOK  (Bx * Nn)          // 4096 tokens
#define BH     (Bx * HEADS)       // 64
#define GBK    16

// ---------------- scratch (device globals; no allocation allowed) -----------
__device__ float gWqm[DH * DIM];                 // (1/16) sum_h w_q rows
__device__ float gScores[Bx * Nn];
__device__ float gGate[Bx * Nn];
__device__ float gAttnOut[Bx * Nn * INNER];      // active rows only

__device__ int   gActIdx[Bx * TOP_K];
__device__ int   gActCount[Bx];
__device__ float gGateC[Bx * TOP_K];
__device__ float gQc[BH * TOP_K * DH];           // compact Q (active only)
__device__ float gKc[BH * TOP_K * DH];           // compact K
__device__ float gVc[BH * TOP_K * DH];           // compact V
__device__ float gXsumP[8 * Bx * DIM];           // partial x sums
__device__ float gXsum[Bx * DIM];                // per-batch sum of x rows
__device__ float gVsumAll[BH * DH];              // = Wv . xsum
__device__ float gInactRow[Bx * DIM];

// ---------------- Kernel 0: fold head-mean into q weights -------------------
__global__ __launch_bounds__(256)
void wqmean_kernel(const float* __restrict__ Wqkv)
{
    const int idx = blockIdx.x * 256 + threadIdx.x;
    const int d = idx >> 10, k = idx & 1023;
    float s = 0.f;
#pragma unroll
    for (int h = 0; h < HEADS; h++)
        s += Wqkv[(size_t)(h * DH + d) * DIM + k];
    gWqm[(size_t)d * DIM + k] = s * (1.0f / 16.0f);
}

// ------- Kernel 1: qmean GEMM (M=4096, N=64, K=1024) + fused gate ----------
__global__ __launch_bounds__(256)
void qmean_gate_kernel(const float* __restrict__ A,
                       const float* __restrict__ ln_g, const float* __restrict__ ln_b,
                       const float* __restrict__ w1, const float* __restrict__ b1,
                       const float* __restrict__ w2, const float* __restrict__ b2)
{
    __shared__ float As[GBK][64 + 4];
    __shared__ float Bs[GBK][64 + 4];
    __shared__ float Qs[64][65];

    const int tid = threadIdx.x;
    const int ty = tid >> 4;
    const int tx = tid & 15;
    const int m0 = blockIdx.x * 64;
    const int lr = tid >> 2;
    const int lc = (tid & 3) * 4;

    float acc[4][4];
#pragma unroll
    for (int i = 0; i < 4; i++)
#pragma unroll
        for (int j = 0; j < 4; j++) acc[i][j] = 0.f;

    for (int k0 = 0; k0 < DIM; k0 += GBK) {
        float4 av = *(const float4*)(A + (size_t)(m0 + lr) * DIM + k0 + lc);
        float4 bv = *(const float4*)(gWqm + (size_t)lr * DIM + k0 + lc);
        As[lc + 0][lr] = av.x; As[lc + 1][lr] = av.y;
        As[lc + 2][lr] = av.z; As[lc + 3][lr] = av.w;
        Bs[lc + 0][lr] = bv.x; Bs[lc + 1][lr] = bv.y;
        Bs[lc + 2][lr] = bv.z; Bs[lc + 3][lr] = bv.w;
        __syncthreads();
#pragma unroll
        for (int kk = 0; kk < GBK; kk++) {
            float4 a = *(const float4*)&As[kk][ty * 4];
            float4 b = *(const float4*)&Bs[kk][tx * 4];
            float ar[4] = {a.x, a.y, a.z, a.w};
            float br[4] = {b.x, b.y, b.z, b.w};
#pragma unroll
            for (int i = 0; i < 4; i++)
#pragma unroll
                for (int j = 0; j < 4; j++) acc[i][j] += ar[i] * br[j];
        }
        __syncthreads();
    }

#pragma unroll
    for (int i = 0; i < 4; i++)
#pragma unroll
        for (int j = 0; j < 4; j++)
            Qs[ty * 4 + i][tx * 4 + j] = acc[i][j];
    __syncthreads();

    // fused gate epilogue: thread t < 64 handles token m0+t
    if (tid < 64) {
        const int t = tid;
        float mu = 0.f, sq = 0.f;
#pragma unroll
        for (int e = 0; e < 64; e++) { float v = Qs[t][e]; mu += v; sq += v * v; }
        mu *= (1.0f / 64.0f);
        const float var = sq * (1.0f / 64.0f) - mu * mu;
        const float rs = rsqrtf(var + LN_EPS);
#pragma unroll
        for (int e = 0; e < 64; e++)
            Qs[t][e] = (Qs[t][e] - mu) * rs * ln_g[e] + ln_b[e];
        float sc = b2[0];
#pragma unroll
        for (int p = 0; p < PROJ_H; p++) {
            float a = b1[p];
#pragma unroll
            for (int e = 0; e < 64; e++) a += Qs[t][e] * w1[p * DH + e];
            float g = 0.5f * a * (1.0f + erff(a * 0.70710678118654752f));
            sc += g * w2[p];
        }
        gScores[m0 + t] = sc;
    }
}

// ------- Kernel 2: radix-select top-k + sigmoid gate + active list ----------
__global__ __launch_bounds__(256)
void topk_gate_kernel()
{
    const int b = blockIdx.x;
    const int tid = threadIdx.x;
    __shared__ uint32_t keys[Nn];
    __shared__ uint32_t hist[256];
    __shared__ uint32_t sPrefix;
    __shared__ int sNeed, cnt;

    for (int t = tid; t < Nn; t += 256) {
        uint32_t u = __float_as_uint(gScores[b * Nn + t]);
        keys[t] = (u & 0x80000000u) ? ~u : (u | 0x80000000u);
    }
    if (tid == 0) { sPrefix = 0; sNeed = TOP_K; cnt = 0; }
    __syncthreads();

#pragma unroll
    for (int shift = 24; shift >= 0; shift -= 8) {
        hist[tid] = 0;
        __syncthreads();
        const uint32_t pref = sPrefix;
        for (int t = tid; t < Nn; t += 256) {
            uint32_t u = keys[t];
            bool match = (shift == 24) || ((u >> (shift + 8)) == pref);
            if (match) atomicAdd(&hist[(u >> shift) & 255u], 1u);
        }
        __syncthreads();
        if (tid == 0) {
            int acc = 0, k = sNeed;
            for (int bin = 255; bin >= 0; bin--) {
                int c = (int)hist[bin];
                if (acc + c >= k) {
                    sPrefix = (pref << 8) | (uint32_t)bin;
                    sNeed = k - acc;
                    break;
                }
                acc += c;
            }
        }
        __syncthreads();
    }

    const uint32_t Tu = sPrefix;
    const float thresh = (Tu & 0x80000000u) ? __uint_as_float(Tu & 0x7FFFFFFFu)
                                            : __uint_as_float(~Tu);

    for (int t = tid; t < Nn; t += 256) {
        float sc = gScores[b * Nn + t];
        float g = 0.0f;
        if (sc >= thresh) {
            int pos = atomicAdd(&cnt, 1);
            if (pos < TOP_K) {
                g = 1.0f / (1.0f + expf(-sc));
                gActIdx[b * TOP_K + pos] = t;
                gGateC[b * TOP_K + pos] = g;
            }
        }
        gGate[b * Nn + t] = g;
    }
    __syncthreads();
    if (tid == 0) gActCount[b] = (cnt < TOP_K) ? cnt : TOP_K;
}

// ---------------- Kernel 3: QKV projection for ACTIVE tokens ----------------
// 128x64 tile, 8x4 per thread. M rows gathered via gActIdx. (R10 verbatim)
__global__ __launch_bounds__(256)
void qkv_active_gemm_kernel(const float* __restrict__ A, const float* __restrict__ Wqkv)
{
    __shared__ float As[GBK][128 + 4];
    __shared__ float Bs[GBK][64 + 4];
    __shared__ int   sidx[128];
    __shared__ int   slive[128];

    const int tid = threadIdx.x;
    const int ty = tid >> 4;
    const int tx = tid & 15;
    const int b  = blockIdx.y >> 1;
    const int mt = blockIdx.y & 1;
    const int n0 = blockIdx.x * 64;

    const int alr = tid >> 1;
    const int alc = (tid & 1) * 8;
    const int blr = tid >> 2;
    const int blc = (tid & 3) * 4;

    const int cnt = gActCount[b];
    if (tid < 128) {
        const int ic = mt * 128 + tid;
        const bool lv = (ic < cnt);
        slive[tid] = lv;
        sidx[tid]  = lv ? gActIdx[b * TOP_K + ic] : gActIdx[b * TOP_K];
    }
    __syncthreads();

    const float* aptr = A + ((size_t)(b * Nn + sidx[alr])) * DIM + alc;
    const float* bptr = Wqkv + (size_t)(n0 + blr) * DIM + blc;

    float acc[8][4];
#pragma unroll
    for (int i = 0; i < 8; i++)
#pragma unroll
        for (int j = 0; j < 4; j++) acc[i][j] = 0.f;

    for (int k0 = 0; k0 < DIM; k0 += GBK) {
        float4 a0 = *(const float4*)(aptr + k0);
        float4 a1 = *(const float4*)(aptr + k0 + 4);
        float4 bv = *(const float4*)(bptr + k0);
#pragma unroll
        for (int i = 0; i < 4; i++) {
            As[alc + i][alr]     = ((const float*)&a0)[i];
            As[alc + 4 + i][alr] = ((const float*)&a1)[i];
            Bs[blc + i][blr]     = ((const float*)&bv)[i];
        }
        __syncthreads();
#pragma unroll
        for (int kk = 0; kk < GBK; kk++) {
            float4 x0 = *(const float4*)&As[kk][ty * 8];
            float4 x1 = *(const float4*)&As[kk][ty * 8 + 4];
            float4 y  = *(const float4*)&Bs[kk][tx * 4];
            float xr[8] = {x0.x, x0.y, x0.z, x0.w, x1.x, x1.y, x1.z, x1.w};
            float yr[4] = {y.x, y.y, y.z, y.w};
#pragma unroll
            for (int i = 0; i < 8; i++)
#pragma unroll
                for (int j = 0; j < 4; j++) acc[i][j] += xr[i] * yr[j];
        }
        __syncthreads();
    }

#pragma unroll
    for (int i = 0; i < 8; i++) {
        const int r = ty * 8 + i;
        if (slive[r]) {
            const int ic = mt * 128 + r;
#pragma unroll
            for (int j = 0; j < 4; j++) {
                const int n = n0 + tx * 4 + j;
                const int which = n >> 10;
                const int inner = n & 1023;
                const int h = inner >> 6, d = inner & 63;
                float* dst = (which == 0) ? gQc : (which == 1) ? gKc : gVc;
                dst[(((size_t)(b * HEADS + h)) * TOP_K + ic) * DH + d] = acc[i][j];
            }
        }
    }
}

// ---------------- Kernel 4a: partial x sums ---------------------------------
__global__ __launch_bounds__(256)
void xsum_part_kernel(const float* __restrict__ x)
{
    const int k = blockIdx.x * 256 + threadIdx.x;
    const int b = blockIdx.y;
    const int sl = blockIdx.z;
    float s = 0.f;
    const float* p = x + ((size_t)b * Nn + sl * 128) * DIM + k;
#pragma unroll 8
    for (int n = 0; n < 128; n++) s += p[(size_t)n * DIM];
    gXsumP[((size_t)sl * Bx + b) * DIM + k] = s;
}

__global__ __launch_bounds__(256)
void xsum_reduce_kernel()
{
    const int k = blockIdx.x * 256 + threadIdx.x;
    const int b = blockIdx.y;
    float s = 0.f;
#pragma unroll
    for (int sl = 0; sl < 8; sl++) s += gXsumP[((size_t)sl * Bx + b) * DIM + k];
    gXsum[b * DIM + k] = s;
}

// ---------------- Kernel 4b: VsumAll = Wv . xsum ----------------------------
__global__ __launch_bounds__(128)
void vsumall_kernel(const float* __restrict__ Wqkv)
{
    const int hd = blockIdx.x;
    const int tid = threadIdx.x;
    const float4* wrow = (const float4*)(Wqkv + (size_t)(2 * INNER + hd) * DIM);

    float acc[Bx] = {0.f, 0.f, 0.f, 0.f};
    for (int c = tid; c < DIM / 4; c += 128) {
        float4 w = wrow[c];
#pragma unroll
        for (int b = 0; b < Bx; b++) {
            float4 v = ((const float4*)(gXsum + b * DIM))[c];
            acc[b] += w.x * v.x + w.y * v.y + w.z * v.z + w.w * v.w;
        }
    }
    __shared__ float red[Bx][128];
#pragma unroll
    for (int b = 0; b < Bx; b++) red[b][tid] = acc[b];
    __syncthreads();
    for (int off = 64; off > 0; off >>= 1) {
        if (tid < off)
#pragma unroll
            for (int b = 0; b < Bx; b++) red[b][tid] += red[b][tid + off];
        __syncthreads();
    }
    if (tid < Bx) gVsumAll[tid * 1024 + hd] = red[tid][0];
}

// ---------------- Kernel 5: attention for ACTIVE queries --------------------
// acc = sum_active (p-1)*Vc; add VsumAll at end (== VsumIn + sum p*Vc). Exact.
#define AT_BJ 64

__global__ __launch_bounds__(128)
void attn_active_kernel()
{
    const int blk = blockIdx.x;
    const int bh = blk >> 1;
    const int half = blk & 1;
    const int b = bh >> 4;
    const int h = bh & 15;
    const int tid = threadIdx.x;
    const int ic = half * 128 + tid;

    const int cnt = gActCount[b];
    const bool live = (ic < cnt);
    const int i = live ? gActIdx[b * TOP_K + ic] : 0;

    __shared__ float4 ksm[AT_BJ][16];
    __shared__ float4 vsm[AT_BJ][16];
    __shared__ float  gsm[AT_BJ];

    float4 q[16];
    {
        const float4* qp = (const float4*)(gQc + ((size_t)bh * TOP_K + ic) * DH);
#pragma unroll
        for (int c = 0; c < 16; c++) q[c] = live ? qp[c] : make_float4(0.f, 0.f, 0.f, 0.f);
    }
    const float gi = live ? gGateC[b * TOP_K + ic] * SCALE : 0.f;

    float4 acc[16];
#pragma unroll
    for (int c = 0; c < 16; c++) acc[c] = make_float4(0.f, 0.f, 0.f, 0.f);
    float l = (float)(Nn - cnt);

    for (int j0 = 0; j0 < cnt; j0 += AT_BJ) {
        const int jn = min(AT_BJ, cnt - j0);
        __syncthreads();
        for (int t = tid; t < AT_BJ * 16; t += 128) {
            int j = t >> 4, c = t & 15;
            if (j < jn) {
                const size_t src = ((size_t)bh * TOP_K + j0 + j) * 16 + c;
                ksm[j][c] = ((const float4*)gKc)[src];
                vsm[j][c] = ((const float4*)gVc)[src];
            }
        }
        if (tid < AT_BJ && tid < jn) gsm[tid] = gGateC[b * TOP_K + j0 + tid];
        __syncthreads();

        for (int j = 0; j < jn; j++) {
            float s = 0.f;
#pragma unroll
            for (int c = 0; c < 16; c++) {
                float4 kv = ksm[j][c];
                s += q[c].x * kv.x + q[c].y * kv.y + q[c].z * kv.z + q[c].w * kv.w;
            }
            float p = __expf(s * gi * gsm[j]);
            l += p;
            const float pm1 = p - 1.0f;
#pragma unroll
            for (int c = 0; c < 16; c++) {
                float4 vv = vsm[j][c];
                acc[c].x += pm1 * vv.x; acc[c].y += pm1 * vv.y;
                acc[c].z += pm1 * vv.z; acc[c].w += pm1 * vv.w;
            }
        }
    }

    if (live) {
        const float inv = 1.0f / l;
        const float4* vall = (const float4*)(gVsumAll + bh * DH);
        float4* orow = (float4*)(gAttnOut + (((size_t)(b * Nn + i)) * HEADS + h) * DH);
#pragma unroll
        for (int c = 0; c < 16; c++) {
            float4 a = acc[c];
            float4 v = vall[c];
            a.x = (a.x + v.x) * inv; a.y = (a.y + v.y) * inv;
            a.z = (a.z + v.z) * inv; a.w = (a.w + v.w) * inv;
            orow[c] = a;
        }
    }
}

// ---------------- Kernel 6a: output projection for ACTIVE rows --------------
// 128x64 tile, 8x4 per thread; M gathered via gActIdx. (R10 verbatim)
__global__ __launch_bounds__(256)
void out_gemm_active_kernel(const float* __restrict__ Bm, const float* __restrict__ bias,
                            float* __restrict__ C)
{
    __shared__ float As[GBK][128 + 4];
    __shared__ float Bs[GBK][64 + 4];
    __shared__ int   sidx[128];
    __shared__ int   slive[128];

    const int tid = threadIdx.x;
    const int ty = tid >> 4;
    const int tx = tid & 15;
    const int b  = blockIdx.y >> 1;
    const int mt = blockIdx.y & 1;
    const int n0 = blockIdx.x * 64;

    const int alr = tid >> 1;
    const int alc = (tid & 1) * 8;
    const int blr = tid >> 2;
    const int blc = (tid & 3) * 4;

    const int cnt = gActCount[b];
    if (tid < 128) {
        const int ic = mt * 128 + tid;
        const bool lv = (ic < cnt);
        slive[tid] = lv;
        sidx[tid]  = lv ? gActIdx[b * TOP_K + ic] : gActIdx[b * TOP_K];
    }
    __syncthreads();

    const float* aptr = gAttnOut + ((size_t)(b * Nn + sidx[alr])) * INNER + alc;
    const float* bptr = Bm + (size_t)(n0 + blr) * INNER + blc;

    float acc[8][4];
#pragma unroll
    for (int i = 0; i < 8; i++)
#pragma unroll
        for (int j = 0; j < 4; j++) acc[i][j] = 0.f;

    for (int k0 = 0; k0 < INNER; k0 += GBK) {
        float4 a0 = *(const float4*)(aptr + k0);
        float4 a1 = *(const float4*)(aptr + k0 + 4);
        float4 bv = *(const float4*)(bptr + k0);
#pragma unroll
        for (int i = 0; i < 4; i++) {
            As[alc + i][alr]     = ((const float*)&a0)[i];
            As[alc + 4 + i][alr] = ((const float*)&a1)[i];
            Bs[blc + i][blr]     = ((const float*)&bv)[i];
        }
        __syncthreads();
#pragma unroll
        for (int kk = 0; kk < GBK; kk++) {
            float4 x0 = *(const float4*)&As[kk][ty * 8];
            float4 x1 = *(const float4*)&As[kk][ty * 8 + 4];
            float4 y  = *(const float4*)&Bs[kk][tx * 4];
            float xr[8] = {x0.x, x0.y, x0.z, x0.w, x1.x, x1.y, x1.z, x1.w};
            float yr[4] = {y.x, y.y, y.z, y.w};
#pragma unroll
            for (int i = 0; i < 8; i++)
#pragma unroll
                for (int j = 0; j < 4; j++) acc[i][j] += xr[i] * yr[j];
        }
        __syncthreads();
    }

#pragma unroll
    for (int i = 0; i < 8; i++) {
        const int r = ty * 8 + i;
        if (slive[r]) {
            const int token = sidx[r];
#pragma unroll
            for (int j = 0; j < 4; j++) {
                const int n = n0 + tx * 4 + j;
                C[((size_t)(b * Nn + token)) * DIM + n] = acc[i][j] + bias[n];
            }
        }
    }
}

// ---------------- Kernel 6b: shared out-row per batch -----------------------
__global__ __launch_bounds__(256)
void inact_row_kernel(const float* __restrict__ Bm, const float* __restrict__ bias)
{
    const int b = blockIdx.y;
    const int n = blockIdx.x * 256 + threadIdx.x;
    const float invN = 1.0f / (float)Nn;

    const float4* vrow = (const float4*)(gVsumAll + b * INNER);
    const float4* wrow = (const float4*)(Bm + (size_t)n * INNER);
    float s = 0.f;
#pragma unroll 8
    for (int c = 0; c < INNER / 4; c++) {
        float4 v = vrow[c];
        float4 w = wrow[c];
        s += v.x * w.x + v.y * w.y + v.z * w.z + v.w * w.w;
    }
    gInactRow[b * DIM + n] = s * invN + bias[n];
}

// ---------------- Kernel 6c: broadcast shared row to inactive tokens --------
__global__ __launch_bounds__(256)
void inact_bcast_kernel(float* __restrict__ C)
{
    const int token = blockIdx.x;
    if (gGate[token] != 0.0f) return;
    const int b = token >> 10;
    const float4* src = (const float4*)(gInactRow + b * DIM);
    float4* dst = (float4*)(C + (size_t)token * DIM);
    for (int c = threadIdx.x; c < DIM / 4; c += 256) dst[c] = src[c];
}

// ---------------- launch ----------------------------------------------------
extern "C" void kernel_launch(void* const* d_in, const int* in_sizes, int n_in,
                              void* d_out, int out_size)
{
    const float* x     = (const float*)d_in[0];
    const float* w_qkv = (const float*)d_in[1];
    const float* w_out = (const float*)d_in[2];
    const float* b_out = (const float*)d_in[3];
    const float* ln_g  = (const float*)d_in[4];
    const float* ln_b  = (const float*)d_in[5];
    const float* w1    = (const float*)d_in[6];
    const float* b1    = (const float*)d_in[7];
    const float* w2    = (const float*)d_in[8];
    const float* b2    = (const float*)d_in[9];
    float* out = (float*)d_out;

    // gate-first
    wqmean_kernel<<<DH * DIM / 256, 256>>>(w_qkv);
    qmean_gate_kernel<<<M_TOK / 64, 256>>>(x, ln_g, ln_b, w1, b1, w2, b2);
    topk_gate_kernel<<<Bx, 256>>>();

    // V sums via linearity
    xsum_part_kernel<<<dim3(DIM / 256, Bx, 8), 256>>>(x);
    xsum_reduce_kernel<<<dim3(DIM / 256, Bx), 256>>>();
    vsumall_kernel<<<DIM, 128>>>(w_qkv);

    // active-token QKV projection straight into compact layout
    qkv_active_gemm_kernel<<<dim3(3 * INNER / 64, Bx * 2), 256>>>(x, w_qkv);

    // attention + output
    attn_active_kernel<<<BH * 2, 128>>>();
    out_gemm_active_kernel<<<dim3(DIM / 64, Bx * 2), 256>>>(w_out, b_out, out);
    inact_row_kernel<<<dim3(DIM / 256, Bx), 256>>>(w_out, b_out);
    inact_bcast_kernel<<<M_TOK, 256>>>(out);
}

// round 13
// speedup vs baseline: 1.5814x; 1.0211x over previous
#include <cuda_runtime.h>
#include <cuda_bf16.h>
#include <cstdint>

// Problem constants
#define Bx     4
#define Nn     1024
#define DIM    1024
#define HEADS  16
#define DH     64
#define INNER  1024
#define PROJ_H 16
#define TOP_K  256
#define SCALE  0.125f
#define LN_EPS 1e-5f

#define M_TOK  (Bx * Nn)          // 4096 tokens
#define BH     (Bx * HEADS)       // 64
#define GBK    16

// ---------------- scratch (device globals; no allocation allowed) -----------
__device__ float gWqm[DH * DIM];                 // (1/16) sum_h w_q rows
__device__ float gScores[Bx * Nn];
__device__ float gGate[Bx * Nn];
__device__ float gAttnOut[Bx * Nn * INNER];      // active rows only

__device__ int   gActIdx[Bx * TOP_K];
__device__ int   gActCount[Bx];
__device__ float gGateC[Bx * TOP_K];
__device__ float gQc[BH * TOP_K * DH];           // compact Q (active only)
__device__ float gKc[BH * TOP_K * DH];           // compact K
__device__ float gVc[BH * TOP_K * DH];           // compact V
__device__ float gXsumP[32 * Bx * DIM];          // partial x sums (32 slabs)
__device__ float gXsum[Bx * DIM];                // per-batch sum of x rows
__device__ float gVsumAll[BH * DH];              // = Wv . xsum
__device__ float gInactRow[Bx * DIM];

// ======== Kernel 1: prep = wqmean (blocks 0..255) + xsum_part (256..767) ====
__global__ __launch_bounds__(256)
void prep_kernel(const float* __restrict__ Wqkv, const float* __restrict__ x)
{
    const int blk = blockIdx.x;
    const int tid = threadIdx.x;
    if (blk < 256) {
        const int idx = blk * 256 + tid;
        const int d = idx >> 10, k = idx & 1023;
        float s = 0.f;
#pragma unroll
        for (int h = 0; h < HEADS; h++)
            s += Wqkv[(size_t)(h * DH + d) * DIM + k];
        gWqm[(size_t)d * DIM + k] = s * (1.0f / 16.0f);
    } else {
        const int e = blk - 256;                 // 0..511
        const int kb = e & 3, b = (e >> 2) & 3, sl = e >> 4;   // sl 0..31
        const int k = kb * 256 + tid;
        float s = 0.f;
        const float* p = x + ((size_t)b * Nn + sl * 32) * DIM + k;
#pragma unroll 8
        for (int n = 0; n < 32; n++) s += p[(size_t)n * DIM];
        gXsumP[((size_t)sl * Bx + b) * DIM + k] = s;
    }
}

// ======== Kernel 2: qmean GEMM (M-tile 32, 128 blocks) + fused gate =========
__global__ __launch_bounds__(256)
void qmean_gate_kernel(const float* __restrict__ A,
                       const float* __restrict__ ln_g, const float* __restrict__ ln_b,
                       const float* __restrict__ w1, const float* __restrict__ b1,
                       const float* __restrict__ w2, const float* __restrict__ b2)
{
    __shared__ float As[GBK][32 + 4];
    __shared__ float Bs[GBK][64 + 4];
    __shared__ float Qs[32][65];

    const int tid = threadIdx.x;
    const int m0 = blockIdx.x * 32;
    const int lr = tid >> 2;           // 0..63
    const int lc = (tid & 3) * 4;
    const int ty = tid >> 4;           // 0..15 -> rows 2ty, 2ty+1
    const int tx = tid & 15;           // cols 4tx..4tx+3

    float acc[2][4];
#pragma unroll
    for (int i = 0; i < 2; i++)
#pragma unroll
        for (int j = 0; j < 4; j++) acc[i][j] = 0.f;

    for (int k0 = 0; k0 < DIM; k0 += GBK) {
        if (lr < 32) {
            float4 av = *(const float4*)(A + (size_t)(m0 + lr) * DIM + k0 + lc);
            As[lc + 0][lr] = av.x; As[lc + 1][lr] = av.y;
            As[lc + 2][lr] = av.z; As[lc + 3][lr] = av.w;
        }
        float4 bv = *(const float4*)(gWqm + (size_t)lr * DIM + k0 + lc);
        Bs[lc + 0][lr] = bv.x; Bs[lc + 1][lr] = bv.y;
        Bs[lc + 2][lr] = bv.z; Bs[lc + 3][lr] = bv.w;
        __syncthreads();
#pragma unroll
        for (int kk = 0; kk < GBK; kk++) {
            float2 a = *(const float2*)&As[kk][ty * 2];
            float4 b = *(const float4*)&Bs[kk][tx * 4];
            float br[4] = {b.x, b.y, b.z, b.w};
#pragma unroll
            for (int j = 0; j < 4; j++) {
                acc[0][j] += a.x * br[j];
                acc[1][j] += a.y * br[j];
            }
        }
        __syncthreads();
    }

#pragma unroll
    for (int i = 0; i < 2; i++)
#pragma unroll
        for (int j = 0; j < 4; j++)
            Qs[ty * 2 + i][tx * 4 + j] = acc[i][j];
    __syncthreads();

    if (tid < 32) {
        const int t = tid;
        float mu = 0.f, sq = 0.f;
#pragma unroll
        for (int e = 0; e < 64; e++) { float v = Qs[t][e]; mu += v; sq += v * v; }
        mu *= (1.0f / 64.0f);
        const float var = sq * (1.0f / 64.0f) - mu * mu;
        const float rs = rsqrtf(var + LN_EPS);
#pragma unroll
        for (int e = 0; e < 64; e++)
            Qs[t][e] = (Qs[t][e] - mu) * rs * ln_g[e] + ln_b[e];
        float sc = b2[0];
#pragma unroll
        for (int p = 0; p < PROJ_H; p++) {
            float a = b1[p];
#pragma unroll
            for (int e = 0; e < 64; e++) a += Qs[t][e] * w1[p * DH + e];
            float g = 0.5f * a * (1.0f + erff(a * 0.70710678118654752f));
            sc += g * w2[p];
        }
        gScores[m0 + t] = sc;
    }
}

// ======== Kernel 3: topk radix-select (0..3) + xsum_reduce (4..19) ==========
__global__ __launch_bounds__(256)
void topk_reduce_kernel()
{
    const int blk = blockIdx.x;
    const int tid = threadIdx.x;

    if (blk >= 4) {                               // xsum_reduce
        const int e = blk - 4;                    // 0..15
        const int b = e >> 2;
        const int k = (e & 3) * 256 + tid;
        float s = 0.f;
#pragma unroll
        for (int sl = 0; sl < 32; sl++)
            s += gXsumP[((size_t)sl * Bx + b) * DIM + k];
        gXsum[b * DIM + k] = s;
        return;
    }

    const int b = blk;
    __shared__ uint32_t keys[Nn];
    __shared__ uint32_t hist[256];
    __shared__ uint32_t sPrefix;
    __shared__ int sNeed, cnt;

    for (int t = tid; t < Nn; t += 256) {
        uint32_t u = __float_as_uint(gScores[b * Nn + t]);
        keys[t] = (u & 0x80000000u) ? ~u : (u | 0x80000000u);
    }
    if (tid == 0) { sPrefix = 0; sNeed = TOP_K; cnt = 0; }
    __syncthreads();

#pragma unroll
    for (int shift = 24; shift >= 0; shift -= 8) {
        hist[tid] = 0;
        __syncthreads();
        const uint32_t pref = sPrefix;
        for (int t = tid; t < Nn; t += 256) {
            uint32_t u = keys[t];
            bool match = (shift == 24) || ((u >> (shift + 8)) == pref);
            if (match) atomicAdd(&hist[(u >> shift) & 255u], 1u);
        }
        __syncthreads();
        if (tid == 0) {
            int acc = 0, k = sNeed;
            for (int bin = 255; bin >= 0; bin--) {
                int c = (int)hist[bin];
                if (acc + c >= k) {
                    sPrefix = (pref << 8) | (uint32_t)bin;
                    sNeed = k - acc;
                    break;
                }
                acc += c;
            }
        }
        __syncthreads();
    }

    const uint32_t Tu = sPrefix;
    const float thresh = (Tu & 0x80000000u) ? __uint_as_float(Tu & 0x7FFFFFFFu)
                                            : __uint_as_float(~Tu);

    for (int t = tid; t < Nn; t += 256) {
        float sc = gScores[b * Nn + t];
        float g = 0.0f;
        if (sc >= thresh) {
            int pos = atomicAdd(&cnt, 1);
            if (pos < TOP_K) {
                g = 1.0f / (1.0f + expf(-sc));
                gActIdx[b * TOP_K + pos] = t;
                gGateC[b * TOP_K + pos] = g;
            }
        }
        gGate[b * Nn + t] = g;
    }
    __syncthreads();
    if (tid == 0) gActCount[b] = (cnt < TOP_K) ? cnt : TOP_K;
}

// ---------------- Kernel 4: VsumAll = Wv . xsum (verbatim R12) --------------
__global__ __launch_bounds__(128)
void vsumall_kernel(const float* __restrict__ Wqkv)
{
    const int hd = blockIdx.x;
    const int tid = threadIdx.x;
    const float4* wrow = (const float4*)(Wqkv + (size_t)(2 * INNER + hd) * DIM);

    float acc[Bx] = {0.f, 0.f, 0.f, 0.f};
    for (int c = tid; c < DIM / 4; c += 128) {
        float4 w = wrow[c];
#pragma unroll
        for (int b = 0; b < Bx; b++) {
            float4 v = ((const float4*)(gXsum + b * DIM))[c];
            acc[b] += w.x * v.x + w.y * v.y + w.z * v.z + w.w * v.w;
        }
    }
    __shared__ float red[Bx][128];
#pragma unroll
    for (int b = 0; b < Bx; b++) red[b][tid] = acc[b];
    __syncthreads();
    for (int off = 64; off > 0; off >>= 1) {
        if (tid < off)
#pragma unroll
            for (int b = 0; b < Bx; b++) red[b][tid] += red[b][tid + off];
        __syncthreads();
    }
    if (tid < Bx) gVsumAll[tid * 1024 + hd] = red[tid][0];
}

// ---------------- Kernel 5: shared out-row per batch (verbatim R12) ---------
__global__ __launch_bounds__(256)
void inact_row_kernel(const float* __restrict__ Bm, const float* __restrict__ bias)
{
    const int b = blockIdx.y;
    const int n = blockIdx.x * 256 + threadIdx.x;
    const float invN = 1.0f / (float)Nn;

    const float4* vrow = (const float4*)(gVsumAll + b * INNER);
    const float4* wrow = (const float4*)(Bm + (size_t)n * INNER);
    float s = 0.f;
#pragma unroll 8
    for (int c = 0; c < INNER / 4; c++) {
        float4 v = vrow[c];
        float4 w = wrow[c];
        s += v.x * w.x + v.y * w.y + v.z * w.z + v.w * w.w;
    }
    gInactRow[b * DIM + n] = s * invN + bias[n];
}

// ---------------- Kernel 6: QKV projection for ACTIVE tokens (verbatim) -----
__global__ __launch_bounds__(256)
void qkv_active_gemm_kernel(const float* __restrict__ A, const float* __restrict__ Wqkv)
{
    __shared__ float As[GBK][128 + 4];
    __shared__ float Bs[GBK][64 + 4];
    __shared__ int   sidx[128];
    __shared__ int   slive[128];

    const int tid = threadIdx.x;
    const int ty = tid >> 4;
    const int tx = tid & 15;
    const int b  = blockIdx.y >> 1;
    const int mt = blockIdx.y & 1;
    const int n0 = blockIdx.x * 64;

    const int alr = tid >> 1;
    const int alc = (tid & 1) * 8;
    const int blr = tid >> 2;
    const int blc = (tid & 3) * 4;

    const int cnt = gActCount[b];
    if (tid < 128) {
        const int ic = mt * 128 + tid;
        const bool lv = (ic < cnt);
        slive[tid] = lv;
        sidx[tid]  = lv ? gActIdx[b * TOP_K + ic] : gActIdx[b * TOP_K];
    }
    __syncthreads();

    const float* aptr = A + ((size_t)(b * Nn + sidx[alr])) * DIM + alc;
    const float* bptr = Wqkv + (size_t)(n0 + blr) * DIM + blc;

    float acc[8][4];
#pragma unroll
    for (int i = 0; i < 8; i++)
#pragma unroll
        for (int j = 0; j < 4; j++) acc[i][j] = 0.f;

    for (int k0 = 0; k0 < DIM; k0 += GBK) {
        float4 a0 = *(const float4*)(aptr + k0);
        float4 a1 = *(const float4*)(aptr + k0 + 4);
        float4 bv = *(const float4*)(bptr + k0);
#pragma unroll
        for (int i = 0; i < 4; i++) {
            As[alc + i][alr]     = ((const float*)&a0)[i];
            As[alc + 4 + i][alr] = ((const float*)&a1)[i];
            Bs[blc + i][blr]     = ((const float*)&bv)[i];
        }
        __syncthreads();
#pragma unroll
        for (int kk = 0; kk < GBK; kk++) {
            float4 x0 = *(const float4*)&As[kk][ty * 8];
            float4 x1 = *(const float4*)&As[kk][ty * 8 + 4];
            float4 y  = *(const float4*)&Bs[kk][tx * 4];
            float xr[8] = {x0.x, x0.y, x0.z, x0.w, x1.x, x1.y, x1.z, x1.w};
            float yr[4] = {y.x, y.y, y.z, y.w};
#pragma unroll
            for (int i = 0; i < 8; i++)
#pragma unroll
                for (int j = 0; j < 4; j++) acc[i][j] += xr[i] * yr[j];
        }
        __syncthreads();
    }

#pragma unroll
    for (int i = 0; i < 8; i++) {
        const int r = ty * 8 + i;
        if (slive[r]) {
            const int ic = mt * 128 + r;
#pragma unroll
            for (int j = 0; j < 4; j++) {
                const int n = n0 + tx * 4 + j;
                const int which = n >> 10;
                const int inner = n & 1023;
                const int h = inner >> 6, d = inner & 63;
                float* dst = (which == 0) ? gQc : (which == 1) ? gKc : gVc;
                dst[(((size_t)(b * HEADS + h)) * TOP_K + ic) * DH + d] = acc[i][j];
            }
        }
    }
}

// ======== Kernel 7: attention (0..127) + inactive broadcast (128..159) ======
#define AT_BJ 64

__global__ __launch_bounds__(128)
void attn_bcast_kernel(float* __restrict__ C)
{
    const int blk = blockIdx.x;
    const int tid = threadIdx.x;

    if (blk >= 128) {                             // bcast: 128 tokens per block
        const int e = blk - 128;                  // 0..31
        for (int s = 0; s < 128; s++) {
            const int token = e * 128 + s;
            if (gGate[token] != 0.0f) continue;
            const int b = token >> 10;
            const float4* src = (const float4*)(gInactRow + b * DIM);
            float4* dst = (float4*)(C + (size_t)token * DIM);
            dst[tid]       = src[tid];
            dst[tid + 128] = src[tid + 128];
        }
        return;
    }

    const int bh = blk >> 1;
    const int half = blk & 1;
    const int b = bh >> 4;
    const int h = bh & 15;
    const int ic = half * 128 + tid;

    const int cnt = gActCount[b];
    const bool live = (ic < cnt);
    const int i = live ? gActIdx[b * TOP_K + ic] : 0;

    __shared__ float4 ksm[AT_BJ][16];
    __shared__ float4 vsm[AT_BJ][16];
    __shared__ float  gsm[AT_BJ];

    float4 q[16];
    {
        const float4* qp = (const float4*)(gQc + ((size_t)bh * TOP_K + ic) * DH);
#pragma unroll
        for (int c = 0; c < 16; c++) q[c] = live ? qp[c] : make_float4(0.f, 0.f, 0.f, 0.f);
    }
    const float gi = live ? gGateC[b * TOP_K + ic] * SCALE : 0.f;

    float4 acc[16];
#pragma unroll
    for (int c = 0; c < 16; c++) acc[c] = make_float4(0.f, 0.f, 0.f, 0.f);
    float l = (float)(Nn - cnt);

    for (int j0 = 0; j0 < cnt; j0 += AT_BJ) {
        const int jn = min(AT_BJ, cnt - j0);
        __syncthreads();
        for (int t = tid; t < AT_BJ * 16; t += 128) {
            int j = t >> 4, c = t & 15;
            if (j < jn) {
                const size_t src = ((size_t)bh * TOP_K + j0 + j) * 16 + c;
                ksm[j][c] = ((const float4*)gKc)[src];
                vsm[j][c] = ((const float4*)gVc)[src];
            }
        }
        if (tid < AT_BJ && tid < jn) gsm[tid] = gGateC[b * TOP_K + j0 + tid];
        __syncthreads();

        for (int j = 0; j < jn; j++) {
            float s = 0.f;
#pragma unroll
            for (int c = 0; c < 16; c++) {
                float4 kv = ksm[j][c];
                s += q[c].x * kv.x + q[c].y * kv.y + q[c].z * kv.z + q[c].w * kv.w;
            }
            float p = __expf(s * gi * gsm[j]);
            l += p;
            const float pm1 = p - 1.0f;
#pragma unroll
            for (int c = 0; c < 16; c++) {
                float4 vv = vsm[j][c];
                acc[c].x += pm1 * vv.x; acc[c].y += pm1 * vv.y;
                acc[c].z += pm1 * vv.z; acc[c].w += pm1 * vv.w;
            }
        }
    }

    if (live) {
        const float inv = 1.0f / l;
        const float4* vall = (const float4*)(gVsumAll + bh * DH);
        float4* orow = (float4*)(gAttnOut + (((size_t)(b * Nn + i)) * HEADS + h) * DH);
#pragma unroll
        for (int c = 0; c < 16; c++) {
            float4 a = acc[c];
            float4 v = vall[c];
            a.x = (a.x + v.x) * inv; a.y = (a.y + v.y) * inv;
            a.z = (a.z + v.z) * inv; a.w = (a.w + v.w) * inv;
            orow[c] = a;
        }
    }
}

// ---------------- Kernel 8: output projection for ACTIVE rows (verbatim) ----
__global__ __launch_bounds__(256)
void out_gemm_active_kernel(const float* __restrict__ Bm, const float* __restrict__ bias,
                            float* __restrict__ C)
{
    __shared__ float As[GBK][128 + 4];
    __shared__ float Bs[GBK][64 + 4];
    __shared__ int   sidx[128];
    __shared__ int   slive[128];

    const int tid = threadIdx.x;
    const int ty = tid >> 4;
    const int tx = tid & 15;
    const int b  = blockIdx.y >> 1;
    const int mt = blockIdx.y & 1;
    const int n0 = blockIdx.x * 64;

    const int alr = tid >> 1;
    const int alc = (tid & 1) * 8;
    const int blr = tid >> 2;
    const int blc = (tid & 3) * 4;

    const int cnt = gActCount[b];
    if (tid < 128) {
        const int ic = mt * 128 + tid;
        const bool lv = (ic < cnt);
        slive[tid] = lv;
        sidx[tid]  = lv ? gActIdx[b * TOP_K + ic] : gActIdx[b * TOP_K];
    }
    __syncthreads();

    const float* aptr = gAttnOut + ((size_t)(b * Nn + sidx[alr])) * INNER + alc;
    const float* bptr = Bm + (size_t)(n0 + blr) * INNER + blc;

    float acc[8][4];
#pragma unroll
    for (int i = 0; i < 8; i++)
#pragma unroll
        for (int j = 0; j < 4; j++) acc[i][j] = 0.f;

    for (int k0 = 0; k0 < INNER; k0 += GBK) {
        float4 a0 = *(const float4*)(aptr + k0);
        float4 a1 = *(const float4*)(aptr + k0 + 4);
        float4 bv = *(const float4*)(bptr + k0);
#pragma unroll
        for (int i = 0; i < 4; i++) {
            As[alc + i][alr]     = ((const float*)&a0)[i];
            As[alc + 4 + i][alr] = ((const float*)&a1)[i];
            Bs[blc + i][blr]     = ((const float*)&bv)[i];
        }
        __syncthreads();
#pragma unroll
        for (int kk = 0; kk < GBK; kk++) {
            float4 x0 = *(const float4*)&As[kk][ty * 8];
            float4 x1 = *(const float4*)&As[kk][ty * 8 + 4];
            float4 y  = *(const float4*)&Bs[kk][tx * 4];
            float xr[8] = {x0.x, x0.y, x0.z, x0.w, x1.x, x1.y, x1.z, x1.w};
            float yr[4] = {y.x, y.y, y.z, y.w};
#pragma unroll
            for (int i = 0; i < 8; i++)
#pragma unroll
                for (int j = 0; j < 4; j++) acc[i][j] += xr[i] * yr[j];
        }
        __syncthreads();
    }

#pragma unroll
    for (int i = 0; i < 8; i++) {
        const int r = ty * 8 + i;
        if (slive[r]) {
            const int token = sidx[r];
#pragma unroll
            for (int j = 0; j < 4; j++) {
                const int n = n0 + tx * 4 + j;
                C[((size_t)(b * Nn + token)) * DIM + n] = acc[i][j] + bias[n];
            }
        }
    }
}

// ---------------- launch ----------------------------------------------------
extern "C" void kernel_launch(void* const* d_in, const int* in_sizes, int n_in,
                              void* d_out, int out_size)
{
    const float* x     = (const float*)d_in[0];
    const float* w_qkv = (const float*)d_in[1];
    const float* w_out = (const float*)d_in[2];
    const float* b_out = (const float*)d_in[3];
    const float* ln_g  = (const float*)d_in[4];
    const float* ln_b  = (const float*)d_in[5];
    const float* w1    = (const float*)d_in[6];
    const float* b1    = (const float*)d_in[7];
    const float* w2    = (const float*)d_in[8];
    const float* b2    = (const float*)d_in[9];
    float* out = (float*)d_out;

    prep_kernel<<<768, 256>>>(w_qkv, x);                          // wqmean + xsum_part
    qmean_gate_kernel<<<M_TOK / 32, 256>>>(x, ln_g, ln_b, w1, b1, w2, b2);
    topk_reduce_kernel<<<20, 256>>>();                            // topk + xsum_reduce
    vsumall_kernel<<<DIM, 128>>>(w_qkv);
    inact_row_kernel<<<dim3(DIM / 256, Bx), 256>>>(w_out, b_out);
    qkv_active_gemm_kernel<<<dim3(3 * INNER / 64, Bx * 2), 256>>>(x, w_qkv);
    attn_bcast_kernel<<<160, 128>>>(out);                         // attn + bcast
    out_gemm_active_kernel<<<dim3(DIM / 64, Bx * 2), 256>>>(w_out, b_out, out);
}

// round 14
// speedup vs baseline: 1.7524x; 1.1082x over previous
#include <cuda_runtime.h>
#include <cuda_bf16.h>
#include <cstdint>

// Problem constants
#define Bx     4
#define Nn     1024
#define DIM    1024
#define HEADS  16
#define DH     64
#define INNER  1024
#define PROJ_H 16
#define TOP_K  256
#define SCALE  0.125f
#define LN_EPS 1e-5f

#define M_TOK  (Bx * Nn)          // 4096 tokens
#define BH     (Bx * HEADS)       // 64
#define GBK    16

// ---------------- scratch (device globals; no allocation allowed) -----------
__device__ float gWqm[DH * DIM];                 // (1/16) sum_h w_q rows
__device__ float gScores[Bx * Nn];
__device__ float gGate[Bx * Nn];
__device__ float gAttnOut[Bx * Nn * INNER];      // active rows only

__device__ int   gActIdx[Bx * TOP_K];
__device__ int   gActCount[Bx];
__device__ float gGateC[Bx * TOP_K];
__device__ float gQc[BH * TOP_K * DH];           // compact Q (active only)
__device__ float gKc[BH * TOP_K * DH];           // compact K
__device__ float gVc[BH * TOP_K * DH];           // compact V
__device__ float gXsumP[32 * Bx * DIM];          // partial x sums (32 slabs)
__device__ float gXsum[Bx * DIM];                // per-batch sum of x rows
__device__ float gVsumAll[BH * DH];              // = Wv . xsum
__device__ float gInactRow[Bx * DIM];

// ======== Kernel 1: prep = wqmean (blocks 0..255) + xsum_part (256..767) ====
__global__ __launch_bounds__(256)
void prep_kernel(const float* __restrict__ Wqkv, const float* __restrict__ x)
{
    const int blk = blockIdx.x;
    const int tid = threadIdx.x;
    if (blk < 256) {
        const int idx = blk * 256 + tid;
        const int d = idx >> 10, k = idx & 1023;
        float s = 0.f;
#pragma unroll
        for (int h = 0; h < HEADS; h++)
            s += Wqkv[(size_t)(h * DH + d) * DIM + k];
        gWqm[(size_t)d * DIM + k] = s * (1.0f / 16.0f);
    } else {
        const int e = blk - 256;                 // 0..511
        const int kb = e & 3, b = (e >> 2) & 3, sl = e >> 4;   // sl 0..31
        const int k = kb * 256 + tid;
        float s = 0.f;
        const float* p = x + ((size_t)b * Nn + sl * 32) * DIM + k;
#pragma unroll 8
        for (int n = 0; n < 32; n++) s += p[(size_t)n * DIM];
        gXsumP[((size_t)sl * Bx + b) * DIM + k] = s;
    }
}

// ======== Kernel 2: qmean GEMM (M-tile 32, 128 blocks) + fused gate =========
__global__ __launch_bounds__(256)
void qmean_gate_kernel(const float* __restrict__ A,
                       const float* __restrict__ ln_g, const float* __restrict__ ln_b,
                       const float* __restrict__ w1, const float* __restrict__ b1,
                       const float* __restrict__ w2, const float* __restrict__ b2)
{
    __shared__ float As[GBK][32 + 4];
    __shared__ float Bs[GBK][64 + 4];
    __shared__ float Qs[32][65];

    const int tid = threadIdx.x;
    const int m0 = blockIdx.x * 32;
    const int lr = tid >> 2;
    const int lc = (tid & 3) * 4;
    const int ty = tid >> 4;
    const int tx = tid & 15;

    float acc[2][4];
#pragma unroll
    for (int i = 0; i < 2; i++)
#pragma unroll
        for (int j = 0; j < 4; j++) acc[i][j] = 0.f;

    for (int k0 = 0; k0 < DIM; k0 += GBK) {
        if (lr < 32) {
            float4 av = *(const float4*)(A + (size_t)(m0 + lr) * DIM + k0 + lc);
            As[lc + 0][lr] = av.x; As[lc + 1][lr] = av.y;
            As[lc + 2][lr] = av.z; As[lc + 3][lr] = av.w;
        }
        float4 bv = *(const float4*)(gWqm + (size_t)lr * DIM + k0 + lc);
        Bs[lc + 0][lr] = bv.x; Bs[lc + 1][lr] = bv.y;
        Bs[lc + 2][lr] = bv.z; Bs[lc + 3][lr] = bv.w;
        __syncthreads();
#pragma unroll
        for (int kk = 0; kk < GBK; kk++) {
            float2 a = *(const float2*)&As[kk][ty * 2];
            float4 b = *(const float4*)&Bs[kk][tx * 4];
            float br[4] = {b.x, b.y, b.z, b.w};
#pragma unroll
            for (int j = 0; j < 4; j++) {
                acc[0][j] += a.x * br[j];
                acc[1][j] += a.y * br[j];
            }
        }
        __syncthreads();
    }

#pragma unroll
    for (int i = 0; i < 2; i++)
#pragma unroll
        for (int j = 0; j < 4; j++)
            Qs[ty * 2 + i][tx * 4 + j] = acc[i][j];
    __syncthreads();

    if (tid < 32) {
        const int t = tid;
        float mu = 0.f, sq = 0.f;
#pragma unroll
        for (int e = 0; e < 64; e++) { float v = Qs[t][e]; mu += v; sq += v * v; }
        mu *= (1.0f / 64.0f);
        const float var = sq * (1.0f / 64.0f) - mu * mu;
        const float rs = rsqrtf(var + LN_EPS);
#pragma unroll
        for (int e = 0; e < 64; e++)
            Qs[t][e] = (Qs[t][e] - mu) * rs * ln_g[e] + ln_b[e];
        float sc = b2[0];
#pragma unroll
        for (int p = 0; p < PROJ_H; p++) {
            float a = b1[p];
#pragma unroll
            for (int e = 0; e < 64; e++) a += Qs[t][e] * w1[p * DH + e];
            float g = 0.5f * a * (1.0f + erff(a * 0.70710678118654752f));
            sc += g * w2[p];
        }
        gScores[m0 + t] = sc;
    }
}

// ======== Kernel 3: topk radix-select (0..3) + xsum_reduce (4..19) ==========
__global__ __launch_bounds__(256)
void topk_reduce_kernel()
{
    const int blk = blockIdx.x;
    const int tid = threadIdx.x;

    if (blk >= 4) {
        const int e = blk - 4;
        const int b = e >> 2;
        const int k = (e & 3) * 256 + tid;
        float s = 0.f;
#pragma unroll
        for (int sl = 0; sl < 32; sl++)
            s += gXsumP[((size_t)sl * Bx + b) * DIM + k];
        gXsum[b * DIM + k] = s;
        return;
    }

    const int b = blk;
    __shared__ uint32_t keys[Nn];
    __shared__ uint32_t hist[256];
    __shared__ uint32_t sPrefix;
    __shared__ int sNeed, cnt;

    for (int t = tid; t < Nn; t += 256) {
        uint32_t u = __float_as_uint(gScores[b * Nn + t]);
        keys[t] = (u & 0x80000000u) ? ~u : (u | 0x80000000u);
    }
    if (tid == 0) { sPrefix = 0; sNeed = TOP_K; cnt = 0; }
    __syncthreads();

#pragma unroll
    for (int shift = 24; shift >= 0; shift -= 8) {
        hist[tid] = 0;
        __syncthreads();
        const uint32_t pref = sPrefix;
        for (int t = tid; t < Nn; t += 256) {
            uint32_t u = keys[t];
            bool match = (shift == 24) || ((u >> (shift + 8)) == pref);
            if (match) atomicAdd(&hist[(u >> shift) & 255u], 1u);
        }
        __syncthreads();
        if (tid == 0) {
            int acc = 0, k = sNeed;
            for (int bin = 255; bin >= 0; bin--) {
                int c = (int)hist[bin];
                if (acc + c >= k) {
                    sPrefix = (pref << 8) | (uint32_t)bin;
                    sNeed = k - acc;
                    break;
                }
                acc += c;
            }
        }
        __syncthreads();
    }

    const uint32_t Tu = sPrefix;
    const float thresh = (Tu & 0x80000000u) ? __uint_as_float(Tu & 0x7FFFFFFFu)
                                            : __uint_as_float(~Tu);

    for (int t = tid; t < Nn; t += 256) {
        float sc = gScores[b * Nn + t];
        float g = 0.0f;
        if (sc >= thresh) {
            int pos = atomicAdd(&cnt, 1);
            if (pos < TOP_K) {
                g = 1.0f / (1.0f + expf(-sc));
                gActIdx[b * TOP_K + pos] = t;
                gGateC[b * TOP_K + pos] = g;
            }
        }
        gGate[b * Nn + t] = g;
    }
    __syncthreads();
    if (tid == 0) gActCount[b] = (cnt < TOP_K) ? cnt : TOP_K;
}

// ---------------- Kernel 4: VsumAll = Wv . xsum -----------------------------
__global__ __launch_bounds__(128)
void vsumall_kernel(const float* __restrict__ Wqkv)
{
    const int hd = blockIdx.x;
    const int tid = threadIdx.x;
    const float4* wrow = (const float4*)(Wqkv + (size_t)(2 * INNER + hd) * DIM);

    float acc[Bx] = {0.f, 0.f, 0.f, 0.f};
    for (int c = tid; c < DIM / 4; c += 128) {
        float4 w = wrow[c];
#pragma unroll
        for (int b = 0; b < Bx; b++) {
            float4 v = ((const float4*)(gXsum + b * DIM))[c];
            acc[b] += w.x * v.x + w.y * v.y + w.z * v.z + w.w * v.w;
        }
    }
    __shared__ float red[Bx][128];
#pragma unroll
    for (int b = 0; b < Bx; b++) red[b][tid] = acc[b];
    __syncthreads();
    for (int off = 64; off > 0; off >>= 1) {
        if (tid < off)
#pragma unroll
            for (int b = 0; b < Bx; b++) red[b][tid] += red[b][tid + off];
        __syncthreads();
    }
    if (tid < Bx) gVsumAll[tid * 1024 + hd] = red[tid][0];
}

// ---------------- Kernel 5: shared out-row per batch ------------------------
__global__ __launch_bounds__(256)
void inact_row_kernel(const float* __restrict__ Bm, const float* __restrict__ bias)
{
    const int b = blockIdx.y;
    const int n = blockIdx.x * 256 + threadIdx.x;
    const float invN = 1.0f / (float)Nn;

    const float4* vrow = (const float4*)(gVsumAll + b * INNER);
    const float4* wrow = (const float4*)(Bm + (size_t)n * INNER);
    float s = 0.f;
#pragma unroll 8
    for (int c = 0; c < INNER / 4; c++) {
        float4 v = vrow[c];
        float4 w = wrow[c];
        s += v.x * w.x + v.y * w.y + v.z * w.z + v.w * w.w;
    }
    gInactRow[b * DIM + n] = s * invN + bias[n];
}

// ---------------- Kernel 6: QKV projection (ACTIVE), double-buffered --------
__global__ __launch_bounds__(256)
void qkv_active_gemm_kernel(const float* __restrict__ A, const float* __restrict__ Wqkv)
{
    __shared__ float As[2][GBK][128 + 4];
    __shared__ float Bs[2][GBK][64 + 4];
    __shared__ int   sidx[128];
    __shared__ int   slive[128];

    const int tid = threadIdx.x;
    const int ty = tid >> 4;
    const int tx = tid & 15;
    const int b  = blockIdx.y >> 1;
    const int mt = blockIdx.y & 1;
    const int n0 = blockIdx.x * 64;

    const int alr = tid >> 1;
    const int alc = (tid & 1) * 8;
    const int blr = tid >> 2;
    const int blc = (tid & 3) * 4;

    const int cnt = gActCount[b];
    if (tid < 128) {
        const int ic = mt * 128 + tid;
        const bool lv = (ic < cnt);
        slive[tid] = lv;
        sidx[tid]  = lv ? gActIdx[b * TOP_K + ic] : gActIdx[b * TOP_K];
    }
    __syncthreads();

    const float* aptr = A + ((size_t)(b * Nn + sidx[alr])) * DIM + alc;
    const float* bptr = Wqkv + (size_t)(n0 + blr) * DIM + blc;

    float acc[8][4];
#pragma unroll
    for (int i = 0; i < 8; i++)
#pragma unroll
        for (int j = 0; j < 4; j++) acc[i][j] = 0.f;

    // preload tile 0
    {
        float4 a0 = *(const float4*)(aptr);
        float4 a1 = *(const float4*)(aptr + 4);
        float4 bv = *(const float4*)(bptr);
#pragma unroll
        for (int i = 0; i < 4; i++) {
            As[0][alc + i][alr]     = ((const float*)&a0)[i];
            As[0][alc + 4 + i][alr] = ((const float*)&a1)[i];
            Bs[0][blc + i][blr]     = ((const float*)&bv)[i];
        }
    }
    __syncthreads();

    int buf = 0;
    for (int k0 = 0; k0 < DIM; k0 += GBK) {
        const bool nxt = (k0 + GBK) < DIM;
        float4 pa0, pa1, pbv;
        if (nxt) {
            pa0 = *(const float4*)(aptr + k0 + GBK);
            pa1 = *(const float4*)(aptr + k0 + GBK + 4);
            pbv = *(const float4*)(bptr + k0 + GBK);
        }
#pragma unroll
        for (int kk = 0; kk < GBK; kk++) {
            float4 x0 = *(const float4*)&As[buf][kk][ty * 8];
            float4 x1 = *(const float4*)&As[buf][kk][ty * 8 + 4];
            float4 y  = *(const float4*)&Bs[buf][kk][tx * 4];
            float xr[8] = {x0.x, x0.y, x0.z, x0.w, x1.x, x1.y, x1.z, x1.w};
            float yr[4] = {y.x, y.y, y.z, y.w};
#pragma unroll
            for (int i = 0; i < 8; i++)
#pragma unroll
                for (int j = 0; j < 4; j++) acc[i][j] += xr[i] * yr[j];
        }
        if (nxt) {
#pragma unroll
            for (int i = 0; i < 4; i++) {
                As[buf ^ 1][alc + i][alr]     = ((const float*)&pa0)[i];
                As[buf ^ 1][alc + 4 + i][alr] = ((const float*)&pa1)[i];
                Bs[buf ^ 1][blc + i][blr]     = ((const float*)&pbv)[i];
            }
            __syncthreads();
            buf ^= 1;
        }
    }

#pragma unroll
    for (int i = 0; i < 8; i++) {
        const int r = ty * 8 + i;
        if (slive[r]) {
            const int ic = mt * 128 + r;
#pragma unroll
            for (int j = 0; j < 4; j++) {
                const int n = n0 + tx * 4 + j;
                const int which = n >> 10;
                const int inner = n & 1023;
                const int h = inner >> 6, d = inner & 63;
                float* dst = (which == 0) ? gQc : (which == 1) ? gKc : gVc;
                dst[(((size_t)(b * HEADS + h)) * TOP_K + ic) * DH + d] = acc[i][j];
            }
        }
    }
}

// ======== Kernel 7: flash attention (0..511) + inactive bcast (512..543) ====
__global__ __launch_bounds__(128)
void attn_flash_kernel(float* __restrict__ C)
{
    const int blk = blockIdx.x;
    const int tid = threadIdx.x;

    if (blk >= 512) {                             // bcast: 128 tokens per block
        const int e = blk - 512;                  // 0..31
        for (int s = 0; s < 128; s++) {
            const int token = e * 128 + s;
            if (gGate[token] != 0.0f) continue;
            const int b = token >> 10;
            const float4* src = (const float4*)(gInactRow + b * DIM);
            float4* dst = (float4*)(C + (size_t)token * DIM);
            dst[tid]       = src[tid];
            dst[tid + 128] = src[tid + 128];
        }
        return;
    }

    const int bh = blk >> 3;        // 0..63
    const int qt = blk & 7;         // q-tile of 32
    const int b  = bh >> 4;
    const int h  = bh & 15;

    __shared__ float Qt[64][36];    // [d][q]   (transposed Q)
    __shared__ float KV[64][68];    // GEMM1: [d][j] (K^T); GEMM2: [j][d] (V)
    __shared__ float Ps[32][68];    // [q][j]  pm1 values
    __shared__ float lsm[32];
    __shared__ float gsm[64];

    const int cnt = gActCount[b];
    const int ty = tid >> 4;        // 0..7  -> q rows ty*4..+3 / d cols
    const int tx = tid & 15;        // 0..15 -> j / d cols tx*4..+3

    // ---- stage Q tile transposed: 32 q x 64 d ----
#pragma unroll
    for (int u = 0; u < 4; u++) {
        const int f = tid * 4 + u;            // 0..511 float4s
        const int q = f >> 4;
        const int c4 = (f & 15) * 4;
        float4 v = *(const float4*)(gQc + ((size_t)bh * TOP_K + qt * 32 + q) * DH + c4);
        Qt[c4 + 0][q] = v.x; Qt[c4 + 1][q] = v.y;
        Qt[c4 + 2][q] = v.z; Qt[c4 + 3][q] = v.w;
    }

    // per-thread query gates (scaled); 0 if dead
    float giq[4];
#pragma unroll
    for (int i = 0; i < 4; i++) {
        const int ic = qt * 32 + ty * 4 + i;
        giq[i] = (ic < cnt) ? gGateC[b * TOP_K + ic] * SCALE : 0.f;
    }

    float acc[4][4];
#pragma unroll
    for (int i = 0; i < 4; i++)
#pragma unroll
        for (int j = 0; j < 4; j++) acc[i][j] = 0.f;
    float lreg = 0.f;               // only meaningful for tid<32

    for (int jt = 0; jt < 4; jt++) {
        const int j0 = jt * 64;
        __syncthreads();            // KV + Ps free for reuse

        // stage K tile transposed [d][j]
#pragma unroll
        for (int u = 0; u < 8; u++) {
            const int f = tid * 8 + u;        // 0..1023 float4s
            const int j = f >> 4;
            const int c4 = (f & 15) * 4;
            float4 v = *(const float4*)(gKc + ((size_t)bh * TOP_K + j0 + j) * DH + c4);
            KV[c4 + 0][j] = v.x; KV[c4 + 1][j] = v.y;
            KV[c4 + 2][j] = v.z; KV[c4 + 3][j] = v.w;
        }
        if (tid < 64)
            gsm[tid] = (j0 + tid < cnt) ? gGateC[b * TOP_K + j0 + tid] : 0.f;
        __syncthreads();

        // GEMM1: S[4q x 4j] = Q . K^T
        float s[4][4];
#pragma unroll
        for (int i = 0; i < 4; i++)
#pragma unroll
            for (int j = 0; j < 4; j++) s[i][j] = 0.f;
#pragma unroll 8
        for (int kk = 0; kk < 64; kk++) {
            float4 a = *(const float4*)&Qt[kk][ty * 4];
            float4 k4 = *(const float4*)&KV[kk][tx * 4];
            float ar[4] = {a.x, a.y, a.z, a.w};
            float kr[4] = {k4.x, k4.y, k4.z, k4.w};
#pragma unroll
            for (int i = 0; i < 4; i++)
#pragma unroll
                for (int j = 0; j < 4; j++) s[i][j] += ar[i] * kr[j];
        }

        // pm1 = exp(s*gi*gj) - 1 ; write Ps[q][j]
        float gjr[4];
#pragma unroll
        for (int j = 0; j < 4; j++) gjr[j] = gsm[tx * 4 + j];
#pragma unroll
        for (int i = 0; i < 4; i++)
#pragma unroll
            for (int j = 0; j < 4; j++)
                Ps[ty * 4 + i][tx * 4 + j] = __expf(s[i][j] * giq[i] * gjr[j]) - 1.0f;
        __syncthreads();            // Ps visible; GEMM1 done with KV

        // row sums (threads 0..31, one query each) + stage V [j][d]
        if (tid < 32) {
            float ls = 0.f;
#pragma unroll 8
            for (int j = 0; j < 64; j++) ls += Ps[tid][j];
            lreg += ls;
        }
#pragma unroll
        for (int u = 0; u < 8; u++) {
            const int f = tid * 8 + u;
            const int j = f >> 4;
            const int c4 = (f & 15) * 4;
            *(float4*)&KV[j][c4] =
                *(const float4*)(gVc + ((size_t)bh * TOP_K + j0 + j) * DH + c4);
        }
        __syncthreads();            // V visible

        // GEMM2: acc[4q x 4d] += Ps . V
#pragma unroll 8
        for (int j = 0; j < 64; j++) {
            float ar[4];
#pragma unroll
            for (int i = 0; i < 4; i++) ar[i] = Ps[ty * 4 + i][j];   // broadcast
            float4 v4 = *(const float4*)&KV[j][tx * 4];
            float vr[4] = {v4.x, v4.y, v4.z, v4.w};
#pragma unroll
            for (int i = 0; i < 4; i++)
#pragma unroll
                for (int jj = 0; jj < 4; jj++) acc[i][jj] += ar[i] * vr[jj];
        }
    }

    if (tid < 32) lsm[tid] = lreg;
    __syncthreads();

    // epilogue: O = (acc + VsumAll) / (Nn + l)
#pragma unroll
    for (int i = 0; i < 4; i++) {
        const int q = ty * 4 + i;
        const int ic = qt * 32 + q;
        if (ic < cnt) {
            const int token = gActIdx[b * TOP_K + ic];
            const float inv = 1.0f / ((float)Nn + lsm[q]);
            float4 vall = *(const float4*)(gVsumAll + bh * DH + tx * 4);
            float4 o;
            o.x = (acc[i][0] + vall.x) * inv;
            o.y = (acc[i][1] + vall.y) * inv;
            o.z = (acc[i][2] + vall.z) * inv;
            o.w = (acc[i][3] + vall.w) * inv;
            *(float4*)(gAttnOut + (((size_t)(b * Nn + token)) * HEADS + h) * DH
                       + tx * 4) = o;
        }
    }
}

// ---------------- Kernel 8: output projection (ACTIVE), double-buffered -----
__global__ __launch_bounds__(256)
void out_gemm_active_kernel(const float* __restrict__ Bm, const float* __restrict__ bias,
                            float* __restrict__ C)
{
    __shared__ float As[2][GBK][128 + 4];
    __shared__ float Bs[2][GBK][64 + 4];
    __shared__ int   sidx[128];
    __shared__ int   slive[128];

    const int tid = threadIdx.x;
    const int ty = tid >> 4;
    const int tx = tid & 15;
    const int b  = blockIdx.y >> 1;
    const int mt = blockIdx.y & 1;
    const int n0 = blockIdx.x * 64;

    const int alr = tid >> 1;
    const int alc = (tid & 1) * 8;
    const int blr = tid >> 2;
    const int blc = (tid & 3) * 4;

    const int cnt = gActCount[b];
    if (tid < 128) {
        const int ic = mt * 128 + tid;
        const bool lv = (ic < cnt);
        slive[tid] = lv;
        sidx[tid]  = lv ? gActIdx[b * TOP_K + ic] : gActIdx[b * TOP_K];
    }
    __syncthreads();

    const float* aptr = gAttnOut + ((size_t)(b * Nn + sidx[alr])) * INNER + alc;
    const float* bptr = Bm + (size_t)(n0 + blr) * INNER + blc;

    float acc[8][4];
#pragma unroll
    for (int i = 0; i < 8; i++)
#pragma unroll
        for (int j = 0; j < 4; j++) acc[i][j] = 0.f;

    {
        float4 a0 = *(const float4*)(aptr);
        float4 a1 = *(const float4*)(aptr + 4);
        float4 bv = *(const float4*)(bptr);
#pragma unroll
        for (int i = 0; i < 4; i++) {
            As[0][alc + i][alr]     = ((const float*)&a0)[i];
            As[0][alc + 4 + i][alr] = ((const float*)&a1)[i];
            Bs[0][blc + i][blr]     = ((const float*)&bv)[i];
        }
    }
    __syncthreads();

    int buf = 0;
    for (int k0 = 0; k0 < INNER; k0 += GBK) {
        const bool nxt = (k0 + GBK) < INNER;
        float4 pa0, pa1, pbv;
        if (nxt) {
            pa0 = *(const float4*)(aptr + k0 + GBK);
            pa1 = *(const float4*)(aptr + k0 + GBK + 4);
            pbv = *(const float4*)(bptr + k0 + GBK);
        }
#pragma unroll
        for (int kk = 0; kk < GBK; kk++) {
            float4 x0 = *(const float4*)&As[buf][kk][ty * 8];
            float4 x1 = *(const float4*)&As[buf][kk][ty * 8 + 4];
            float4 y  = *(const float4*)&Bs[buf][kk][tx * 4];
            float xr[8] = {x0.x, x0.y, x0.z, x0.w, x1.x, x1.y, x1.z, x1.w};
            float yr[4] = {y.x, y.y, y.z, y.w};
#pragma unroll
            for (int i = 0; i < 8; i++)
#pragma unroll
                for (int j = 0; j < 4; j++) acc[i][j] += xr[i] * yr[j];
        }
        if (nxt) {
#pragma unroll
            for (int i = 0; i < 4; i++) {
                As[buf ^ 1][alc + i][alr]     = ((const float*)&pa0)[i];
                As[buf ^ 1][alc + 4 + i][alr] = ((const float*)&pa1)[i];
                Bs[buf ^ 1][blc + i][blr]     = ((const float*)&pbv)[i];
            }
            __syncthreads();
            buf ^= 1;
        }
    }

#pragma unroll
    for (int i = 0; i < 8; i++) {
        const int r = ty * 8 + i;
        if (slive[r]) {
            const int token = sidx[r];
#pragma unroll
            for (int j = 0; j < 4; j++) {
                const int n = n0 + tx * 4 + j;
                C[((size_t)(b * Nn + token)) * DIM + n] = acc[i][j] + bias[n];
            }
        }
    }
}

// ---------------- launch ----------------------------------------------------
extern "C" void kernel_launch(void* const* d_in, const int* in_sizes, int n_in,
                              void* d_out, int out_size)
{
    const float* x     = (const float*)d_in[0];
    const float* w_qkv = (const float*)d_in[1];
    const float* w_out = (const float*)d_in[2];
    const float* b_out = (const float*)d_in[3];
    const float* ln_g  = (const float*)d_in[4];
    const float* ln_b  = (const float*)d_in[5];
    const float* w1    = (const float*)d_in[6];
    const float* b1    = (const float*)d_in[7];
    const float* w2    = (const float*)d_in[8];
    const float* b2    = (const float*)d_in[9];
    float* out = (float*)d_out;

    prep_kernel<<<768, 256>>>(w_qkv, x);
    qmean_gate_kernel<<<M_TOK / 32, 256>>>(x, ln_g, ln_b, w1, b1, w2, b2);
    topk_reduce_kernel<<<20, 256>>>();
    vsumall_kernel<<<DIM, 128>>>(w_qkv);
    inact_row_kernel<<<dim3(DIM / 256, Bx), 256>>>(w_out, b_out);
    qkv_active_gemm_kernel<<<dim3(3 * INNER / 64, Bx * 2), 256>>>(x, w_qkv);
    attn_flash_kernel<<<544, 128>>>(out);
    out_gemm_active_kernel<<<dim3(DIM / 64, Bx * 2), 256>>>(w_out, b_out, out);
}

// round 15
// speedup vs baseline: 1.7622x; 1.0056x over previous
#include <cuda_runtime.h>
#include <cuda_bf16.h>
#include <cstdint>

// Problem constants
#define Bx     4
#define Nn     1024
#define DIM    1024
#define HEADS  16
#define DH     64
#define INNER  1024
#define PROJ_H 16
#define TOP_K  256
#define SCALE  0.125f
#define LN_EPS 1e-5f

#define M_TOK  (Bx * Nn)          // 4096 tokens
#define BH     (Bx * HEADS)       // 64
#define GBK    16

// ---------------- scratch (device globals; no allocation allowed) -----------
__device__ float gWqm[DH * DIM];                 // (1/16) sum_h w_q rows
__device__ float gScores[Bx * Nn];
__device__ float gGate[Bx * Nn];
__device__ float gAttnOut[Bx * Nn * INNER];      // active rows only

__device__ int   gActIdx[Bx * TOP_K];
__device__ int   gActCount[Bx];
__device__ float gGateC[Bx * TOP_K];
__device__ float gQc[BH * TOP_K * DH];           // compact Q (active only)
__device__ float gKc[BH * TOP_K * DH];           // compact K
__device__ float gVc[BH * TOP_K * DH];           // compact V
__device__ float gXsumP[32 * Bx * DIM];          // partial x sums (32 slabs)
__device__ float gXsum[Bx * DIM];                // per-batch sum of x rows
__device__ float gVsumAll[BH * DH];              // = Wv . xsum
__device__ float gInactRow[Bx * DIM];

// ======== Kernel 1: prep = wqmean float4 (0..63) + xsum_part (64..575) ======
__global__ __launch_bounds__(256)
void prep_kernel(const float* __restrict__ Wqkv, const float* __restrict__ x)
{
    const int blk = blockIdx.x;
    const int tid = threadIdx.x;
    if (blk < 64) {
        const int f = blk * 256 + tid;           // float4 index, 0..16383
        const int d = f >> 8;                    // 0..63
        const int k4 = (f & 255) * 4;
        float4 s = make_float4(0.f, 0.f, 0.f, 0.f);
#pragma unroll
        for (int h = 0; h < HEADS; h++) {
            float4 v = *(const float4*)(Wqkv + (size_t)(h * DH + d) * DIM + k4);
            s.x += v.x; s.y += v.y; s.z += v.z; s.w += v.w;
        }
        s.x *= (1.0f / 16.0f); s.y *= (1.0f / 16.0f);
        s.z *= (1.0f / 16.0f); s.w *= (1.0f / 16.0f);
        *(float4*)(gWqm + (size_t)d * DIM + k4) = s;
    } else {
        const int e = blk - 64;                  // 0..511
        const int kb = e & 3, b = (e >> 2) & 3, sl = e >> 4;   // sl 0..31
        const int k = kb * 256 + tid;
        float s = 0.f;
        const float* p = x + ((size_t)b * Nn + sl * 32) * DIM + k;
#pragma unroll 8
        for (int n = 0; n < 32; n++) s += p[(size_t)n * DIM];
        gXsumP[((size_t)sl * Bx + b) * DIM + k] = s;
    }
}

// ==== Kernel 2: qmean GEMM + fused gate (0..127) + xsum_reduce (128..143) ===
__global__ __launch_bounds__(256)
void qmean_gate_kernel(const float* __restrict__ A,
                       const float* __restrict__ ln_g, const float* __restrict__ ln_b,
                       const float* __restrict__ w1, const float* __restrict__ b1,
                       const float* __restrict__ w2, const float* __restrict__ b2)
{
    const int blk = blockIdx.x;
    const int tid = threadIdx.x;

    if (blk >= 128) {                             // xsum_reduce
        const int e = blk - 128;                  // 0..15
        const int b = e >> 2;
        const int k = (e & 3) * 256 + tid;
        float s = 0.f;
#pragma unroll
        for (int sl = 0; sl < 32; sl++)
            s += gXsumP[((size_t)sl * Bx + b) * DIM + k];
        gXsum[b * DIM + k] = s;
        return;
    }

    __shared__ float As[GBK][32 + 4];
    __shared__ float Bs[GBK][64 + 4];
    __shared__ float Qs[32][65];

    const int m0 = blk * 32;
    const int lr = tid >> 2;
    const int lc = (tid & 3) * 4;
    const int ty = tid >> 4;
    const int tx = tid & 15;

    float acc[2][4];
#pragma unroll
    for (int i = 0; i < 2; i++)
#pragma unroll
        for (int j = 0; j < 4; j++) acc[i][j] = 0.f;

    for (int k0 = 0; k0 < DIM; k0 += GBK) {
        if (lr < 32) {
            float4 av = *(const float4*)(A + (size_t)(m0 + lr) * DIM + k0 + lc);
            As[lc + 0][lr] = av.x; As[lc + 1][lr] = av.y;
            As[lc + 2][lr] = av.z; As[lc + 3][lr] = av.w;
        }
        float4 bv = *(const float4*)(gWqm + (size_t)lr * DIM + k0 + lc);
        Bs[lc + 0][lr] = bv.x; Bs[lc + 1][lr] = bv.y;
        Bs[lc + 2][lr] = bv.z; Bs[lc + 3][lr] = bv.w;
        __syncthreads();
#pragma unroll
        for (int kk = 0; kk < GBK; kk++) {
            float2 a = *(const float2*)&As[kk][ty * 2];
            float4 b = *(const float4*)&Bs[kk][tx * 4];
            float br[4] = {b.x, b.y, b.z, b.w};
#pragma unroll
            for (int j = 0; j < 4; j++) {
                acc[0][j] += a.x * br[j];
                acc[1][j] += a.y * br[j];
            }
        }
        __syncthreads();
    }

#pragma unroll
    for (int i = 0; i < 2; i++)
#pragma unroll
        for (int j = 0; j < 4; j++)
            Qs[ty * 2 + i][tx * 4 + j] = acc[i][j];
    __syncthreads();

    if (tid < 32) {
        const int t = tid;
        float mu = 0.f, sq = 0.f;
#pragma unroll
        for (int e = 0; e < 64; e++) { float v = Qs[t][e]; mu += v; sq += v * v; }
        mu *= (1.0f / 64.0f);
        const float var = sq * (1.0f / 64.0f) - mu * mu;
        const float rs = rsqrtf(var + LN_EPS);
#pragma unroll
        for (int e = 0; e < 64; e++)
            Qs[t][e] = (Qs[t][e] - mu) * rs * ln_g[e] + ln_b[e];
        float sc = b2[0];
#pragma unroll
        for (int p = 0; p < PROJ_H; p++) {
            float a = b1[p];
#pragma unroll
            for (int e = 0; e < 64; e++) a += Qs[t][e] * w1[p * DH + e];
            float g = 0.5f * a * (1.0f + erff(a * 0.70710678118654752f));
            sc += g * w2[p];
        }
        gScores[m0 + t] = sc;
    }
}

// ===== Kernel 3: topk radix-select (0..3) + vsumall (blocks 4..1027) ========
__global__ __launch_bounds__(256)
void topk_vsum_kernel(const float* __restrict__ Wqkv)
{
    const int blk = blockIdx.x;
    const int tid = threadIdx.x;

    if (blk >= 4) {                               // vsumall: hd = blk-4
        const int hd = blk - 4;
        __shared__ float red[Bx][256];
        const float4* wrow = (const float4*)(Wqkv + (size_t)(2 * INNER + hd) * DIM);
        float4 w = wrow[tid];
#pragma unroll
        for (int b = 0; b < Bx; b++) {
            float4 v = ((const float4*)(gXsum + b * DIM))[tid];
            red[b][tid] = w.x * v.x + w.y * v.y + w.z * v.z + w.w * v.w;
        }
        __syncthreads();
        for (int off = 128; off > 0; off >>= 1) {
            if (tid < off)
#pragma unroll
                for (int b = 0; b < Bx; b++) red[b][tid] += red[b][tid + off];
            __syncthreads();
        }
        if (tid < Bx) gVsumAll[tid * 1024 + hd] = red[tid][0];
        return;
    }

    const int b = blk;
    __shared__ uint32_t keys[Nn];
    __shared__ uint32_t hist[256];
    __shared__ uint32_t sPrefix;
    __shared__ int sNeed, cnt;

    for (int t = tid; t < Nn; t += 256) {
        uint32_t u = __float_as_uint(gScores[b * Nn + t]);
        keys[t] = (u & 0x80000000u) ? ~u : (u | 0x80000000u);
    }
    if (tid == 0) { sPrefix = 0; sNeed = TOP_K; cnt = 0; }
    __syncthreads();

#pragma unroll
    for (int shift = 24; shift >= 0; shift -= 8) {
        hist[tid] = 0;
        __syncthreads();
        const uint32_t pref = sPrefix;
        for (int t = tid; t < Nn; t += 256) {
            uint32_t u = keys[t];
            bool match = (shift == 24) || ((u >> (shift + 8)) == pref);
            if (match) atomicAdd(&hist[(u >> shift) & 255u], 1u);
        }
        __syncthreads();
        if (tid == 0) {
            int acc = 0, k = sNeed;
            for (int bin = 255; bin >= 0; bin--) {
                int c = (int)hist[bin];
                if (acc + c >= k) {
                    sPrefix = (pref << 8) | (uint32_t)bin;
                    sNeed = k - acc;
                    break;
                }
                acc += c;
            }
        }
        __syncthreads();
    }

    const uint32_t Tu = sPrefix;
    const float thresh = (Tu & 0x80000000u) ? __uint_as_float(Tu & 0x7FFFFFFFu)
                                            : __uint_as_float(~Tu);

    for (int t = tid; t < Nn; t += 256) {
        float sc = gScores[b * Nn + t];
        float g = 0.0f;
        if (sc >= thresh) {
            int pos = atomicAdd(&cnt, 1);
            if (pos < TOP_K) {
                g = 1.0f / (1.0f + expf(-sc));
                gActIdx[b * TOP_K + pos] = t;
                gGateC[b * TOP_K + pos] = g;
            }
        }
        gGate[b * Nn + t] = g;
    }
    __syncthreads();
    if (tid == 0) gActCount[b] = (cnt < TOP_K) ? cnt : TOP_K;
}

// ---------------- Kernel 4: shared out-row per batch ------------------------
__global__ __launch_bounds__(256)
void inact_row_kernel(const float* __restrict__ Bm, const float* __restrict__ bias)
{
    const int b = blockIdx.y;
    const int n = blockIdx.x * 256 + threadIdx.x;
    const float invN = 1.0f / (float)Nn;

    const float4* vrow = (const float4*)(gVsumAll + b * INNER);
    const float4* wrow = (const float4*)(Bm + (size_t)n * INNER);
    float s = 0.f;
#pragma unroll 8
    for (int c = 0; c < INNER / 4; c++) {
        float4 v = vrow[c];
        float4 w = wrow[c];
        s += v.x * w.x + v.y * w.y + v.z * w.z + v.w * w.w;
    }
    gInactRow[b * DIM + n] = s * invN + bias[n];
}

// ---------------- Kernel 5: QKV projection (ACTIVE), double-buffered --------
__global__ __launch_bounds__(256)
void qkv_active_gemm_kernel(const float* __restrict__ A, const float* __restrict__ Wqkv)
{
    __shared__ float As[2][GBK][128 + 4];
    __shared__ float Bs[2][GBK][64 + 4];
    __shared__ int   sidx[128];
    __shared__ int   slive[128];

    const int tid = threadIdx.x;
    const int ty = tid >> 4;
    const int tx = tid & 15;
    const int b  = blockIdx.y >> 1;
    const int mt = blockIdx.y & 1;
    const int n0 = blockIdx.x * 64;

    const int alr = tid >> 1;
    const int alc = (tid & 1) * 8;
    const int blr = tid >> 2;
    const int blc = (tid & 3) * 4;

    const int cnt = gActCount[b];
    if (tid < 128) {
        const int ic = mt * 128 + tid;
        const bool lv = (ic < cnt);
        slive[tid] = lv;
        sidx[tid]  = lv ? gActIdx[b * TOP_K + ic] : gActIdx[b * TOP_K];
    }
    __syncthreads();

    const float* aptr = A + ((size_t)(b * Nn + sidx[alr])) * DIM + alc;
    const float* bptr = Wqkv + (size_t)(n0 + blr) * DIM + blc;

    float acc[8][4];
#pragma unroll
    for (int i = 0; i < 8; i++)
#pragma unroll
        for (int j = 0; j < 4; j++) acc[i][j] = 0.f;

    {
        float4 a0 = *(const float4*)(aptr);
        float4 a1 = *(const float4*)(aptr + 4);
        float4 bv = *(const float4*)(bptr);
#pragma unroll
        for (int i = 0; i < 4; i++) {
            As[0][alc + i][alr]     = ((const float*)&a0)[i];
            As[0][alc + 4 + i][alr] = ((const float*)&a1)[i];
            Bs[0][blc + i][blr]     = ((const float*)&bv)[i];
        }
    }
    __syncthreads();

    int buf = 0;
    for (int k0 = 0; k0 < DIM; k0 += GBK) {
        const bool nxt = (k0 + GBK) < DIM;
        float4 pa0, pa1, pbv;
        if (nxt) {
            pa0 = *(const float4*)(aptr + k0 + GBK);
            pa1 = *(const float4*)(aptr + k0 + GBK + 4);
            pbv = *(const float4*)(bptr + k0 + GBK);
        }
#pragma unroll
        for (int kk = 0; kk < GBK; kk++) {
            float4 x0 = *(const float4*)&As[buf][kk][ty * 8];
            float4 x1 = *(const float4*)&As[buf][kk][ty * 8 + 4];
            float4 y  = *(const float4*)&Bs[buf][kk][tx * 4];
            float xr[8] = {x0.x, x0.y, x0.z, x0.w, x1.x, x1.y, x1.z, x1.w};
            float yr[4] = {y.x, y.y, y.z, y.w};
#pragma unroll
            for (int i = 0; i < 8; i++)
#pragma unroll
                for (int j = 0; j < 4; j++) acc[i][j] += xr[i] * yr[j];
        }
        if (nxt) {
#pragma unroll
            for (int i = 0; i < 4; i++) {
                As[buf ^ 1][alc + i][alr]     = ((const float*)&pa0)[i];
                As[buf ^ 1][alc + 4 + i][alr] = ((const float*)&pa1)[i];
                Bs[buf ^ 1][blc + i][blr]     = ((const float*)&pbv)[i];
            }
            __syncthreads();
            buf ^= 1;
        }
    }

#pragma unroll
    for (int i = 0; i < 8; i++) {
        const int r = ty * 8 + i;
        if (slive[r]) {
            const int ic = mt * 128 + r;
#pragma unroll
            for (int j = 0; j < 4; j++) {
                const int n = n0 + tx * 4 + j;
                const int which = n >> 10;
                const int inner = n & 1023;
                const int h = inner >> 6, d = inner & 63;
                float* dst = (which == 0) ? gQc : (which == 1) ? gKc : gVc;
                dst[(((size_t)(b * HEADS + h)) * TOP_K + ic) * DH + d] = acc[i][j];
            }
        }
    }
}

// ======== Kernel 6: flash attention (0..511) + inactive bcast (512..543) ====
__global__ __launch_bounds__(128)
void attn_flash_kernel(float* __restrict__ C)
{
    const int blk = blockIdx.x;
    const int tid = threadIdx.x;

    if (blk >= 512) {                             // bcast: 128 tokens per block
        const int e = blk - 512;                  // 0..31
        for (int s = 0; s < 128; s++) {
            const int token = e * 128 + s;
            if (gGate[token] != 0.0f) continue;
            const int b = token >> 10;
            const float4* src = (const float4*)(gInactRow + b * DIM);
            float4* dst = (float4*)(C + (size_t)token * DIM);
            dst[tid]       = src[tid];
            dst[tid + 128] = src[tid + 128];
        }
        return;
    }

    const int bh = blk >> 3;
    const int qt = blk & 7;
    const int b  = bh >> 4;
    const int h  = bh & 15;

    __shared__ float Qt[64][36];    // [d][q]
    __shared__ float KV[64][68];    // GEMM1: [d][j] (K^T); GEMM2: [j][d] (V)
    __shared__ float Ps[32][68];    // [q][j] pm1
    __shared__ float lsm[32];
    __shared__ float gsm[64];

    const int cnt = gActCount[b];
    const int ty = tid >> 4;
    const int tx = tid & 15;

#pragma unroll
    for (int u = 0; u < 4; u++) {
        const int f = tid * 4 + u;
        const int q = f >> 4;
        const int c4 = (f & 15) * 4;
        float4 v = *(const float4*)(gQc + ((size_t)bh * TOP_K + qt * 32 + q) * DH + c4);
        Qt[c4 + 0][q] = v.x; Qt[c4 + 1][q] = v.y;
        Qt[c4 + 2][q] = v.z; Qt[c4 + 3][q] = v.w;
    }

    float giq[4];
#pragma unroll
    for (int i = 0; i < 4; i++) {
        const int ic = qt * 32 + ty * 4 + i;
        giq[i] = (ic < cnt) ? gGateC[b * TOP_K + ic] * SCALE : 0.f;
    }

    float acc[4][4];
#pragma unroll
    for (int i = 0; i < 4; i++)
#pragma unroll
        for (int j = 0; j < 4; j++) acc[i][j] = 0.f;
    float lacc[4] = {0.f, 0.f, 0.f, 0.f};        // row-sum accum (valid at tx==0)

    for (int jt = 0; jt < 4; jt++) {
        const int j0 = jt * 64;
        __syncthreads();

#pragma unroll
        for (int u = 0; u < 8; u++) {
            const int f = tid * 8 + u;
            const int j = f >> 4;
            const int c4 = (f & 15) * 4;
            float4 v = *(const float4*)(gKc + ((size_t)bh * TOP_K + j0 + j) * DH + c4);
            KV[c4 + 0][j] = v.x; KV[c4 + 1][j] = v.y;
            KV[c4 + 2][j] = v.z; KV[c4 + 3][j] = v.w;
        }
        if (tid < 64)
            gsm[tid] = (j0 + tid < cnt) ? gGateC[b * TOP_K + j0 + tid] : 0.f;
        __syncthreads();

        float s[4][4];
#pragma unroll
        for (int i = 0; i < 4; i++)
#pragma unroll
            for (int j = 0; j < 4; j++) s[i][j] = 0.f;
#pragma unroll 8
        for (int kk = 0; kk < 64; kk++) {
            float4 a = *(const float4*)&Qt[kk][ty * 4];
            float4 k4 = *(const float4*)&KV[kk][tx * 4];
            float ar[4] = {a.x, a.y, a.z, a.w};
            float kr[4] = {k4.x, k4.y, k4.z, k4.w};
#pragma unroll
            for (int i = 0; i < 4; i++)
#pragma unroll
                for (int j = 0; j < 4; j++) s[i][j] += ar[i] * kr[j];
        }

        float gjr[4];
#pragma unroll
        for (int j = 0; j < 4; j++) gjr[j] = gsm[tx * 4 + j];
        float rs[4];
#pragma unroll
        for (int i = 0; i < 4; i++) {
            float r = 0.f;
#pragma unroll
            for (int j = 0; j < 4; j++) {
                float p = __expf(s[i][j] * giq[i] * gjr[j]) - 1.0f;
                Ps[ty * 4 + i][tx * 4 + j] = p;
                r += p;
            }
            rs[i] = r;
        }
        // shuffle-reduce over the 16 tx lanes (same warp: tid&15)
#pragma unroll
        for (int m = 8; m > 0; m >>= 1)
#pragma unroll
            for (int i = 0; i < 4; i++)
                rs[i] += __shfl_xor_sync(0xFFFFFFFFu, rs[i], m, 16);
        if (tx == 0)
#pragma unroll
            for (int i = 0; i < 4; i++) lacc[i] += rs[i];
        __syncthreads();

        // stage V [j][d]
#pragma unroll
        for (int u = 0; u < 8; u++) {
            const int f = tid * 8 + u;
            const int j = f >> 4;
            const int c4 = (f & 15) * 4;
            *(float4*)&KV[j][c4] =
                *(const float4*)(gVc + ((size_t)bh * TOP_K + j0 + j) * DH + c4);
        }
        __syncthreads();

#pragma unroll 8
        for (int j = 0; j < 64; j++) {
            float ar[4];
#pragma unroll
            for (int i = 0; i < 4; i++) ar[i] = Ps[ty * 4 + i][j];
            float4 v4 = *(const float4*)&KV[j][tx * 4];
            float vr[4] = {v4.x, v4.y, v4.z, v4.w};
#pragma unroll
            for (int i = 0; i < 4; i++)
#pragma unroll
                for (int jj = 0; jj < 4; jj++) acc[i][jj] += ar[i] * vr[jj];
        }
    }

    if (tx == 0)
#pragma unroll
        for (int i = 0; i < 4; i++) lsm[ty * 4 + i] = lacc[i];
    __syncthreads();

#pragma unroll
    for (int i = 0; i < 4; i++) {
        const int q = ty * 4 + i;
        const int ic = qt * 32 + q;
        if (ic < cnt) {
            const int token = gActIdx[b * TOP_K + ic];
            const float inv = 1.0f / ((float)Nn + lsm[q]);
            float4 vall = *(const float4*)(gVsumAll + bh * DH + tx * 4);
            float4 o;
            o.x = (acc[i][0] + vall.x) * inv;
            o.y = (acc[i][1] + vall.y) * inv;
            o.z = (acc[i][2] + vall.z) * inv;
            o.w = (acc[i][3] + vall.w) * inv;
            *(float4*)(gAttnOut + (((size_t)(b * Nn + token)) * HEADS + h) * DH
                       + tx * 4) = o;
        }
    }
}

// ---------------- Kernel 7: output projection (ACTIVE), double-buffered -----
__global__ __launch_bounds__(256)
void out_gemm_active_kernel(const float* __restrict__ Bm, const float* __restrict__ bias,
                            float* __restrict__ C)
{
    __shared__ float As[2][GBK][128 + 4];
    __shared__ float Bs[2][GBK][64 + 4];
    __shared__ int   sidx[128];
    __shared__ int   slive[128];

    const int tid = threadIdx.x;
    const int ty = tid >> 4;
    const int tx = tid & 15;
    const int b  = blockIdx.y >> 1;
    const int mt = blockIdx.y & 1;
    const int n0 = blockIdx.x * 64;

    const int alr = tid >> 1;
    const int alc = (tid & 1) * 8;
    const int blr = tid >> 2;
    const int blc = (tid & 3) * 4;

    const int cnt = gActCount[b];
    if (tid < 128) {
        const int ic = mt * 128 + tid;
        const bool lv = (ic < cnt);
        slive[tid] = lv;
        sidx[tid]  = lv ? gActIdx[b * TOP_K + ic] : gActIdx[b * TOP_K];
    }
    __syncthreads();

    const float* aptr = gAttnOut + ((size_t)(b * Nn + sidx[alr])) * INNER + alc;
    const float* bptr = Bm + (size_t)(n0 + blr) * INNER + blc;

    float acc[8][4];
#pragma unroll
    for (int i = 0; i < 8; i++)
#pragma unroll
        for (int j = 0; j < 4; j++) acc[i][j] = 0.f;

    {
        float4 a0 = *(const float4*)(aptr);
        float4 a1 = *(const float4*)(aptr + 4);
        float4 bv = *(const float4*)(bptr);
#pragma unroll
        for (int i = 0; i < 4; i++) {
            As[0][alc + i][alr]     = ((const float*)&a0)[i];
            As[0][alc + 4 + i][alr] = ((const float*)&a1)[i];
            Bs[0][blc + i][blr]     = ((const float*)&bv)[i];
        }
    }
    __syncthreads();

    int buf = 0;
    for (int k0 = 0; k0 < INNER; k0 += GBK) {
        const bool nxt = (k0 + GBK) < INNER;
        float4 pa0, pa1, pbv;
        if (nxt) {
            pa0 = *(const float4*)(aptr + k0 + GBK);
            pa1 = *(const float4*)(aptr + k0 + GBK + 4);
            pbv = *(const float4*)(bptr + k0 + GBK);
        }
#pragma unroll
        for (int kk = 0; kk < GBK; kk++) {
            float4 x0 = *(const float4*)&As[buf][kk][ty * 8];
            float4 x1 = *(const float4*)&As[buf][kk][ty * 8 + 4];
            float4 y  = *(const float4*)&Bs[buf][kk][tx * 4];
            float xr[8] = {x0.x, x0.y, x0.z, x0.w, x1.x, x1.y, x1.z, x1.w};
            float yr[4] = {y.x, y.y, y.z, y.w};
#pragma unroll
            for (int i = 0; i < 8; i++)
#pragma unroll
                for (int j = 0; j < 4; j++) acc[i][j] += xr[i] * yr[j];
        }
        if (nxt) {
#pragma unroll
            for (int i = 0; i < 4; i++) {
                As[buf ^ 1][alc + i][alr]     = ((const float*)&pa0)[i];
                As[buf ^ 1][alc + 4 + i][alr] = ((const float*)&pa1)[i];
                Bs[buf ^ 1][blc + i][blr]     = ((const float*)&pbv)[i];
            }
            __syncthreads();
            buf ^= 1;
        }
    }

#pragma unroll
    for (int i = 0; i < 8; i++) {
        const int r = ty * 8 + i;
        if (slive[r]) {
            const int token = sidx[r];
#pragma unroll
            for (int j = 0; j < 4; j++) {
                const int n = n0 + tx * 4 + j;
                C[((size_t)(b * Nn + token)) * DIM + n] = acc[i][j] + bias[n];
            }
        }
    }
}

// ---------------- launch ----------------------------------------------------
extern "C" void kernel_launch(void* const* d_in, const int* in_sizes, int n_in,
                              void* d_out, int out_size)
{
    const float* x     = (const float*)d_in[0];
    const float* w_qkv = (const float*)d_in[1];
    const float* w_out = (const float*)d_in[2];
    const float* b_out = (const float*)d_in[3];
    const float* ln_g  = (const float*)d_in[4];
    const float* ln_b  = (const float*)d_in[5];
    const float* w1    = (const float*)d_in[6];
    const float* b1    = (const float*)d_in[7];
    const float* w2    = (const float*)d_in[8];
    const float* b2    = (const float*)d_in[9];
    float* out = (float*)d_out;

    prep_kernel<<<576, 256>>>(w_qkv, x);                          // wqmean + xsum_part
    qmean_gate_kernel<<<144, 256>>>(x, ln_g, ln_b, w1, b1, w2, b2); // qmean+gate + xsum_reduce
    topk_vsum_kernel<<<1028, 256>>>(w_qkv);                       // topk + vsumall
    inact_row_kernel<<<dim3(DIM / 256, Bx), 256>>>(w_out, b_out);
    qkv_active_gemm_kernel<<<dim3(3 * INNER / 64, Bx * 2), 256>>>(x, w_qkv);
    attn_flash_kernel<<<544, 128>>>(out);                         // attn + bcast
    out_gemm_active_kernel<<<dim3(DIM / 64, Bx * 2), 256>>>(w_out, b_out, out);
}

// round 16
// speedup vs baseline: 1.9302x; 1.0953x over previous
#include <cuda_runtime.h>
#include <cuda_bf16.h>
#include <cstdint>

// Problem constants
#define Bx     4
#define Nn     1024
#define DIM    1024
#define HEADS  16
#define DH     64
#define INNER  1024
#define PROJ_H 16
#define TOP_K  256
#define SCALE  0.125f
#define LN_EPS 1e-5f

#define M_TOK  (Bx * Nn)          // 4096 tokens
#define BH     (Bx * HEADS)       // 64
#define GBK    16

// ---------------- scratch (device globals; no allocation allowed) -----------
__device__ float gWqm[DH * DIM];                 // (1/16) sum_h w_q rows
__device__ float gScores[Bx * Nn];
__device__ float gGate[Bx * Nn];
__device__ float gAttnOut[Bx * Nn * INNER];      // active rows only

__device__ int   gActIdx[Bx * TOP_K];
__device__ int   gActCount[Bx];
__device__ float gGateC[Bx * TOP_K];
__device__ float gQc[BH * TOP_K * DH];           // compact Q (active only)
__device__ float gKc[BH * TOP_K * DH];           // compact K
__device__ float gVc[BH * TOP_K * DH];           // compact V
__device__ float gXsumP[32 * Bx * DIM];          // partial x sums (32 slabs)
__device__ float gXsum[Bx * DIM];                // per-batch sum of x rows
__device__ float gVsumAll[BH * DH];              // = Wv . xsum
__device__ float gInactRow[Bx * DIM];

// ======== Kernel 1: prep = wqmean float4 (0..63) + xsum_part (64..575) ======
__global__ __launch_bounds__(256)
void prep_kernel(const float* __restrict__ Wqkv, const float* __restrict__ x)
{
    const int blk = blockIdx.x;
    const int tid = threadIdx.x;
    if (blk < 64) {
        const int f = blk * 256 + tid;           // float4 index, 0..16383
        const int d = f >> 8;                    // 0..63
        const int k4 = (f & 255) * 4;
        float4 s = make_float4(0.f, 0.f, 0.f, 0.f);
#pragma unroll
        for (int h = 0; h < HEADS; h++) {
            float4 v = *(const float4*)(Wqkv + (size_t)(h * DH + d) * DIM + k4);
            s.x += v.x; s.y += v.y; s.z += v.z; s.w += v.w;
        }
        s.x *= (1.0f / 16.0f); s.y *= (1.0f / 16.0f);
        s.z *= (1.0f / 16.0f); s.w *= (1.0f / 16.0f);
        *(float4*)(gWqm + (size_t)d * DIM + k4) = s;
    } else {
        const int e = blk - 64;                  // 0..511
        const int kb = e & 3, b = (e >> 2) & 3, sl = e >> 4;   // sl 0..31
        const int k = kb * 256 + tid;
        float s = 0.f;
        const float* p = x + ((size_t)b * Nn + sl * 32) * DIM + k;
#pragma unroll 8
        for (int n = 0; n < 32; n++) s += p[(size_t)n * DIM];
        gXsumP[((size_t)sl * Bx + b) * DIM + k] = s;
    }
}

// ==== Kernel 2: qmean GEMM + fused gate (0..127) + xsum_reduce (128..143) ===
__global__ __launch_bounds__(256)
void qmean_gate_kernel(const float* __restrict__ A,
                       const float* __restrict__ ln_g, const float* __restrict__ ln_b,
                       const float* __restrict__ w1, const float* __restrict__ b1,
                       const float* __restrict__ w2, const float* __restrict__ b2)
{
    const int blk = blockIdx.x;
    const int tid = threadIdx.x;

    if (blk >= 128) {                             // xsum_reduce
        const int e = blk - 128;                  // 0..15
        const int b = e >> 2;
        const int k = (e & 3) * 256 + tid;
        float s = 0.f;
#pragma unroll
        for (int sl = 0; sl < 32; sl++)
            s += gXsumP[((size_t)sl * Bx + b) * DIM + k];
        gXsum[b * DIM + k] = s;
        return;
    }

    __shared__ float As[GBK][32 + 4];
    __shared__ float Bs[GBK][64 + 4];
    __shared__ float Qs[32][65];

    const int m0 = blk * 32;
    const int lr = tid >> 2;
    const int lc = (tid & 3) * 4;
    const int ty = tid >> 4;
    const int tx = tid & 15;

    float acc[2][4];
#pragma unroll
    for (int i = 0; i < 2; i++)
#pragma unroll
        for (int j = 0; j < 4; j++) acc[i][j] = 0.f;

    for (int k0 = 0; k0 < DIM; k0 += GBK) {
        if (lr < 32) {
            float4 av = *(const float4*)(A + (size_t)(m0 + lr) * DIM + k0 + lc);
            As[lc + 0][lr] = av.x; As[lc + 1][lr] = av.y;
            As[lc + 2][lr] = av.z; As[lc + 3][lr] = av.w;
        }
        float4 bv = *(const float4*)(gWqm + (size_t)lr * DIM + k0 + lc);
        Bs[lc + 0][lr] = bv.x; Bs[lc + 1][lr] = bv.y;
        Bs[lc + 2][lr] = bv.z; Bs[lc + 3][lr] = bv.w;
        __syncthreads();
#pragma unroll
        for (int kk = 0; kk < GBK; kk++) {
            float2 a = *(const float2*)&As[kk][ty * 2];
            float4 b = *(const float4*)&Bs[kk][tx * 4];
            float br[4] = {b.x, b.y, b.z, b.w};
#pragma unroll
            for (int j = 0; j < 4; j++) {
                acc[0][j] += a.x * br[j];
                acc[1][j] += a.y * br[j];
            }
        }
        __syncthreads();
    }

#pragma unroll
    for (int i = 0; i < 2; i++)
#pragma unroll
        for (int j = 0; j < 4; j++)
            Qs[ty * 2 + i][tx * 4 + j] = acc[i][j];
    __syncthreads();

    if (tid < 32) {
        const int t = tid;
        float mu = 0.f, sq = 0.f;
#pragma unroll
        for (int e = 0; e < 64; e++) { float v = Qs[t][e]; mu += v; sq += v * v; }
        mu *= (1.0f / 64.0f);
        const float var = sq * (1.0f / 64.0f) - mu * mu;
        const float rs = rsqrtf(var + LN_EPS);
#pragma unroll
        for (int e = 0; e < 64; e++)
            Qs[t][e] = (Qs[t][e] - mu) * rs * ln_g[e] + ln_b[e];
        float sc = b2[0];
#pragma unroll
        for (int p = 0; p < PROJ_H; p++) {
            float a = b1[p];
#pragma unroll
            for (int e = 0; e < 64; e++) a += Qs[t][e] * w1[p * DH + e];
            float g = 0.5f * a * (1.0f + erff(a * 0.70710678118654752f));
            sc += g * w2[p];
        }
        gScores[m0 + t] = sc;
    }
}

// ===== Kernel 3: topk radix-select (0..3) + vsumall (blocks 4..1027) ========
__global__ __launch_bounds__(256)
void topk_vsum_kernel(const float* __restrict__ Wqkv)
{
    const int blk = blockIdx.x;
    const int tid = threadIdx.x;

    if (blk >= 4) {                               // vsumall: hd = blk-4
        const int hd = blk - 4;
        __shared__ float red[Bx][256];
        const float4* wrow = (const float4*)(Wqkv + (size_t)(2 * INNER + hd) * DIM);
        float4 w = wrow[tid];
#pragma unroll
        for (int b = 0; b < Bx; b++) {
            float4 v = ((const float4*)(gXsum + b * DIM))[tid];
            red[b][tid] = w.x * v.x + w.y * v.y + w.z * v.z + w.w * v.w;
        }
        __syncthreads();
        for (int off = 128; off > 0; off >>= 1) {
            if (tid < off)
#pragma unroll
                for (int b = 0; b < Bx; b++) red[b][tid] += red[b][tid + off];
            __syncthreads();
        }
        if (tid < Bx) gVsumAll[tid * 1024 + hd] = red[tid][0];
        return;
    }

    const int b = blk;
    __shared__ uint32_t keys[Nn];
    __shared__ uint32_t hist[256];
    __shared__ uint32_t sPrefix;
    __shared__ int sNeed, cnt;

    for (int t = tid; t < Nn; t += 256) {
        uint32_t u = __float_as_uint(gScores[b * Nn + t]);
        keys[t] = (u & 0x80000000u) ? ~u : (u | 0x80000000u);
    }
    if (tid == 0) { sPrefix = 0; sNeed = TOP_K; cnt = 0; }
    __syncthreads();

#pragma unroll
    for (int shift = 24; shift >= 0; shift -= 8) {
        hist[tid] = 0;
        __syncthreads();
        const uint32_t pref = sPrefix;
        for (int t = tid; t < Nn; t += 256) {
            uint32_t u = keys[t];
            bool match = (shift == 24) || ((u >> (shift + 8)) == pref);
            if (match) atomicAdd(&hist[(u >> shift) & 255u], 1u);
        }
        __syncthreads();
        if (tid == 0) {
            int acc = 0, k = sNeed;
            for (int bin = 255; bin >= 0; bin--) {
                int c = (int)hist[bin];
                if (acc + c >= k) {
                    sPrefix = (pref << 8) | (uint32_t)bin;
                    sNeed = k - acc;
                    break;
                }
                acc += c;
            }
        }
        __syncthreads();
    }

    const uint32_t Tu = sPrefix;
    const float thresh = (Tu & 0x80000000u) ? __uint_as_float(Tu & 0x7FFFFFFFu)
                                            : __uint_as_float(~Tu);

    for (int t = tid; t < Nn; t += 256) {
        float sc = gScores[b * Nn + t];
        float g = 0.0f;
        if (sc >= thresh) {
            int pos = atomicAdd(&cnt, 1);
            if (pos < TOP_K) {
                g = 1.0f / (1.0f + expf(-sc));
                gActIdx[b * TOP_K + pos] = t;
                gGateC[b * TOP_K + pos] = g;
            }
        }
        gGate[b * Nn + t] = g;
    }
    __syncthreads();
    if (tid == 0) gActCount[b] = (cnt < TOP_K) ? cnt : TOP_K;
}

// ---- Kernel 4: shared out-row per batch (vsumall-style, 1024 blocks) -------
__global__ __launch_bounds__(256)
void inact_row_kernel(const float* __restrict__ Bm, const float* __restrict__ bias)
{
    const int n = blockIdx.x;                    // 0..1023
    const int tid = threadIdx.x;
    __shared__ float red[Bx][256];

    const float4 w = ((const float4*)(Bm + (size_t)n * INNER))[tid];
#pragma unroll
    for (int b = 0; b < Bx; b++) {
        float4 v = ((const float4*)(gVsumAll + b * INNER))[tid];
        red[b][tid] = w.x * v.x + w.y * v.y + w.z * v.z + w.w * v.w;
    }
    __syncthreads();
    for (int off = 128; off > 0; off >>= 1) {
        if (tid < off)
#pragma unroll
            for (int b = 0; b < Bx; b++) red[b][tid] += red[b][tid + off];
        __syncthreads();
    }
    if (tid < Bx)
        gInactRow[tid * DIM + n] = red[tid][0] * (1.0f / (float)Nn) + bias[n];
}

// ---------------- Kernel 5: QKV projection (ACTIVE), double-buffered --------
__global__ __launch_bounds__(256)
void qkv_active_gemm_kernel(const float* __restrict__ A, const float* __restrict__ Wqkv)
{
    __shared__ float As[2][GBK][128 + 4];
    __shared__ float Bs[2][GBK][64 + 4];
    __shared__ int   sidx[128];
    __shared__ int   slive[128];

    const int tid = threadIdx.x;
    const int ty = tid >> 4;
    const int tx = tid & 15;
    const int b  = blockIdx.y >> 1;
    const int mt = blockIdx.y & 1;
    const int n0 = blockIdx.x * 64;

    const int alr = tid >> 1;
    const int alc = (tid & 1) * 8;
    const int blr = tid >> 2;
    const int blc = (tid & 3) * 4;

    const int cnt = gActCount[b];
    if (tid < 128) {
        const int ic = mt * 128 + tid;
        const bool lv = (ic < cnt);
        slive[tid] = lv;
        sidx[tid]  = lv ? gActIdx[b * TOP_K + ic] : gActIdx[b * TOP_K];
    }
    __syncthreads();

    const float* aptr = A + ((size_t)(b * Nn + sidx[alr])) * DIM + alc;
    const float* bptr = Wqkv + (size_t)(n0 + blr) * DIM + blc;

    float acc[8][4];
#pragma unroll
    for (int i = 0; i < 8; i++)
#pragma unroll
        for (int j = 0; j < 4; j++) acc[i][j] = 0.f;

    {
        float4 a0 = *(const float4*)(aptr);
        float4 a1 = *(const float4*)(aptr + 4);
        float4 bv = *(const float4*)(bptr);
#pragma unroll
        for (int i = 0; i < 4; i++) {
            As[0][alc + i][alr]     = ((const float*)&a0)[i];
            As[0][alc + 4 + i][alr] = ((const float*)&a1)[i];
            Bs[0][blc + i][blr]     = ((const float*)&bv)[i];
        }
    }
    __syncthreads();

    int buf = 0;
    for (int k0 = 0; k0 < DIM; k0 += GBK) {
        const bool nxt = (k0 + GBK) < DIM;
        float4 pa0, pa1, pbv;
        if (nxt) {
            pa0 = *(const float4*)(aptr + k0 + GBK);
            pa1 = *(const float4*)(aptr + k0 + GBK + 4);
            pbv = *(const float4*)(bptr + k0 + GBK);
        }
#pragma unroll
        for (int kk = 0; kk < GBK; kk++) {
            float4 x0 = *(const float4*)&As[buf][kk][ty * 8];
            float4 x1 = *(const float4*)&As[buf][kk][ty * 8 + 4];
            float4 y  = *(const float4*)&Bs[buf][kk][tx * 4];
            float xr[8] = {x0.x, x0.y, x0.z, x0.w, x1.x, x1.y, x1.z, x1.w};
            float yr[4] = {y.x, y.y, y.z, y.w};
#pragma unroll
            for (int i = 0; i < 8; i++)
#pragma unroll
                for (int j = 0; j < 4; j++) acc[i][j] += xr[i] * yr[j];
        }
        if (nxt) {
#pragma unroll
            for (int i = 0; i < 4; i++) {
                As[buf ^ 1][alc + i][alr]     = ((const float*)&pa0)[i];
                As[buf ^ 1][alc + 4 + i][alr] = ((const float*)&pa1)[i];
                Bs[buf ^ 1][blc + i][blr]     = ((const float*)&pbv)[i];
            }
            __syncthreads();
            buf ^= 1;
        }
    }

#pragma unroll
    for (int i = 0; i < 8; i++) {
        const int r = ty * 8 + i;
        if (slive[r]) {
            const int ic = mt * 128 + r;
#pragma unroll
            for (int j = 0; j < 4; j++) {
                const int n = n0 + tx * 4 + j;
                const int which = n >> 10;
                const int inner = n & 1023;
                const int h = inner >> 6, d = inner & 63;
                float* dst = (which == 0) ? gQc : (which == 1) ? gKc : gVc;
                dst[(((size_t)(b * HEADS + h)) * TOP_K + ic) * DH + d] = acc[i][j];
            }
        }
    }
}

// ======== Kernel 6: flash attention (0..511) + inactive bcast (512..543) ====
__global__ __launch_bounds__(128)
void attn_flash_kernel(float* __restrict__ C)
{
    const int blk = blockIdx.x;
    const int tid = threadIdx.x;

    if (blk >= 512) {                             // bcast: 128 tokens per block
        const int e = blk - 512;                  // 0..31
        for (int s = 0; s < 128; s++) {
            const int token = e * 128 + s;
            if (gGate[token] != 0.0f) continue;
            const int b = token >> 10;
            const float4* src = (const float4*)(gInactRow + b * DIM);
            float4* dst = (float4*)(C + (size_t)token * DIM);
            dst[tid]       = src[tid];
            dst[tid + 128] = src[tid + 128];
        }
        return;
    }

    const int bh = blk >> 3;
    const int qt = blk & 7;
    const int b  = bh >> 4;
    const int h  = bh & 15;

    __shared__ float Qt[64][36];    // [d][q]
    __shared__ float KV[64][68];    // GEMM1: [d][j] (K^T); GEMM2: [j][d] (V)
    __shared__ float Ps[32][68];    // [q][j] pm1
    __shared__ float lsm[32];
    __shared__ float gsm[64];

    const int cnt = gActCount[b];
    const int ty = tid >> 4;
    const int tx = tid & 15;

#pragma unroll
    for (int u = 0; u < 4; u++) {
        const int f = tid * 4 + u;
        const int q = f >> 4;
        const int c4 = (f & 15) * 4;
        float4 v = *(const float4*)(gQc + ((size_t)bh * TOP_K + qt * 32 + q) * DH + c4);
        Qt[c4 + 0][q] = v.x; Qt[c4 + 1][q] = v.y;
        Qt[c4 + 2][q] = v.z; Qt[c4 + 3][q] = v.w;
    }

    float giq[4];
#pragma unroll
    for (int i = 0; i < 4; i++) {
        const int ic = qt * 32 + ty * 4 + i;
        giq[i] = (ic < cnt) ? gGateC[b * TOP_K + ic] * SCALE : 0.f;
    }

    float acc[4][4];
#pragma unroll
    for (int i = 0; i < 4; i++)
#pragma unroll
        for (int j = 0; j < 4; j++) acc[i][j] = 0.f;
    float lacc[4] = {0.f, 0.f, 0.f, 0.f};

    for (int jt = 0; jt < 4; jt++) {
        const int j0 = jt * 64;
        __syncthreads();

#pragma unroll
        for (int u = 0; u < 8; u++) {
            const int f = tid * 8 + u;
            const int j = f >> 4;
            const int c4 = (f & 15) * 4;
            float4 v = *(const float4*)(gKc + ((size_t)bh * TOP_K + j0 + j) * DH + c4);
            KV[c4 + 0][j] = v.x; KV[c4 + 1][j] = v.y;
            KV[c4 + 2][j] = v.z; KV[c4 + 3][j] = v.w;
        }
        if (tid < 64)
            gsm[tid] = (j0 + tid < cnt) ? gGateC[b * TOP_K + j0 + tid] : 0.f;
        __syncthreads();

        float s[4][4];
#pragma unroll
        for (int i = 0; i < 4; i++)
#pragma unroll
            for (int j = 0; j < 4; j++) s[i][j] = 0.f;
#pragma unroll 8
        for (int kk = 0; kk < 64; kk++) {
            float4 a = *(const float4*)&Qt[kk][ty * 4];
            float4 k4 = *(const float4*)&KV[kk][tx * 4];
            float ar[4] = {a.x, a.y, a.z, a.w};
            float kr[4] = {k4.x, k4.y, k4.z, k4.w};
#pragma unroll
            for (int i = 0; i < 4; i++)
#pragma unroll
                for (int j = 0; j < 4; j++) s[i][j] += ar[i] * kr[j];
        }

        float gjr[4];
#pragma unroll
        for (int j = 0; j < 4; j++) gjr[j] = gsm[tx * 4 + j];
        float rs[4];
#pragma unroll
        for (int i = 0; i < 4; i++) {
            float r = 0.f;
#pragma unroll
            for (int j = 0; j < 4; j++) {
                float p = __expf(s[i][j] * giq[i] * gjr[j]) - 1.0f;
                Ps[ty * 4 + i][tx * 4 + j] = p;
                r += p;
            }
            rs[i] = r;
        }
#pragma unroll
        for (int m = 8; m > 0; m >>= 1)
#pragma unroll
            for (int i = 0; i < 4; i++)
                rs[i] += __shfl_xor_sync(0xFFFFFFFFu, rs[i], m, 16);
        if (tx == 0)
#pragma unroll
            for (int i = 0; i < 4; i++) lacc[i] += rs[i];
        __syncthreads();

#pragma unroll
        for (int u = 0; u < 8; u++) {
            const int f = tid * 8 + u;
            const int j = f >> 4;
            const int c4 = (f & 15) * 4;
            *(float4*)&KV[j][c4] =
                *(const float4*)(gVc + ((size_t)bh * TOP_K + j0 + j) * DH + c4);
        }
        __syncthreads();

#pragma unroll 8
        for (int j = 0; j < 64; j++) {
            float ar[4];
#pragma unroll
            for (int i = 0; i < 4; i++) ar[i] = Ps[ty * 4 + i][j];
            float4 v4 = *(const float4*)&KV[j][tx * 4];
            float vr[4] = {v4.x, v4.y, v4.z, v4.w};
#pragma unroll
            for (int i = 0; i < 4; i++)
#pragma unroll
                for (int jj = 0; jj < 4; jj++) acc[i][jj] += ar[i] * vr[jj];
        }
    }

    if (tx == 0)
#pragma unroll
        for (int i = 0; i < 4; i++) lsm[ty * 4 + i] = lacc[i];
    __syncthreads();

#pragma unroll
    for (int i = 0; i < 4; i++) {
        const int q = ty * 4 + i;
        const int ic = qt * 32 + q;
        if (ic < cnt) {
            const int token = gActIdx[b * TOP_K + ic];
            const float inv = 1.0f / ((float)Nn + lsm[q]);
            float4 vall = *(const float4*)(gVsumAll + bh * DH + tx * 4);
            float4 o;
            o.x = (acc[i][0] + vall.x) * inv;
            o.y = (acc[i][1] + vall.y) * inv;
            o.z = (acc[i][2] + vall.z) * inv;
            o.w = (acc[i][3] + vall.w) * inv;
            *(float4*)(gAttnOut + (((size_t)(b * Nn + token)) * HEADS + h) * DH
                       + tx * 4) = o;
        }
    }
}

// ---------------- Kernel 7: output projection (ACTIVE), double-buffered -----
__global__ __launch_bounds__(256)
void out_gemm_active_kernel(const float* __restrict__ Bm, const float* __restrict__ bias,
                            float* __restrict__ C)
{
    __shared__ float As[2][GBK][128 + 4];
    __shared__ float Bs[2][GBK][64 + 4];
    __shared__ int   sidx[128];
    __shared__ int   slive[128];

    const int tid = threadIdx.x;
    const int ty = tid >> 4;
    const int tx = tid & 15;
    const int b  = blockIdx.y >> 1;
    const int mt = blockIdx.y & 1;
    const int n0 = blockIdx.x * 64;

    const int alr = tid >> 1;
    const int alc = (tid & 1) * 8;
    const int blr = tid >> 2;
    const int blc = (tid & 3) * 4;

    const int cnt = gActCount[b];
    if (tid < 128) {
        const int ic = mt * 128 + tid;
        const bool lv = (ic < cnt);
        slive[tid] = lv;
        sidx[tid]  = lv ? gActIdx[b * TOP_K + ic] : gActIdx[b * TOP_K];
    }
    __syncthreads();

    const float* aptr = gAttnOut + ((size_t)(b * Nn + sidx[alr])) * INNER + alc;
    const float* bptr = Bm + (size_t)(n0 + blr) * INNER + blc;

    float acc[8][4];
#pragma unroll
    for (int i = 0; i < 8; i++)
#pragma unroll
        for (int j = 0; j < 4; j++) acc[i][j] = 0.f;

    {
        float4 a0 = *(const float4*)(aptr);
        float4 a1 = *(const float4*)(aptr + 4);
        float4 bv = *(const float4*)(bptr);
#pragma unroll
        for (int i = 0; i < 4; i++) {
            As[0][alc + i][alr]     = ((const float*)&a0)[i];
            As[0][alc + 4 + i][alr] = ((const float*)&a1)[i];
            Bs[0][blc + i][blr]     = ((const float*)&bv)[i];
        }
    }
    __syncthreads();

    int buf = 0;
    for (int k0 = 0; k0 < INNER; k0 += GBK) {
        const bool nxt = (k0 + GBK) < INNER;
        float4 pa0, pa1, pbv;
        if (nxt) {
            pa0 = *(const float4*)(aptr + k0 + GBK);
            pa1 = *(const float4*)(aptr + k0 + GBK + 4);
            pbv = *(const float4*)(bptr + k0 + GBK);
        }
#pragma unroll
        for (int kk = 0; kk < GBK; kk++) {
            float4 x0 = *(const float4*)&As[buf][kk][ty * 8];
            float4 x1 = *(const float4*)&As[buf][kk][ty * 8 + 4];
            float4 y  = *(const float4*)&Bs[buf][kk][tx * 4];
            float xr[8] = {x0.x, x0.y, x0.z, x0.w, x1.x, x1.y, x1.z, x1.w};
            float yr[4] = {y.x, y.y, y.z, y.w};
#pragma unroll
            for (int i = 0; i < 8; i++)
#pragma unroll
                for (int j = 0; j < 4; j++) acc[i][j] += xr[i] * yr[j];
        }
        if (nxt) {
#pragma unroll
            for (int i = 0; i < 4; i++) {
                As[buf ^ 1][alc + i][alr]     = ((const float*)&pa0)[i];
                As[buf ^ 1][alc + 4 + i][alr] = ((const float*)&pa1)[i];
                Bs[buf ^ 1][blc + i][blr]     = ((const float*)&pbv)[i];
            }
            __syncthreads();
            buf ^= 1;
        }
    }

#pragma unroll
    for (int i = 0; i < 8; i++) {
        const int r = ty * 8 + i;
        if (slive[r]) {
            const int token = sidx[r];
#pragma unroll
            for (int j = 0; j < 4; j++) {
                const int n = n0 + tx * 4 + j;
                C[((size_t)(b * Nn + token)) * DIM + n] = acc[i][j] + bias[n];
            }
        }
    }
}

// ---------------- launch ----------------------------------------------------
extern "C" void kernel_launch(void* const* d_in, const int* in_sizes, int n_in,
                              void* d_out, int out_size)
{
    const float* x     = (const float*)d_in[0];
    const float* w_qkv = (const float*)d_in[1];
    const float* w_out = (const float*)d_in[2];
    const float* b_out = (const float*)d_in[3];
    const float* ln_g  = (const float*)d_in[4];
    const float* ln_b  = (const float*)d_in[5];
    const float* w1    = (const float*)d_in[6];
    const float* b1    = (const float*)d_in[7];
    const float* w2    = (const float*)d_in[8];
    const float* b2    = (const float*)d_in[9];
    float* out = (float*)d_out;

    prep_kernel<<<576, 256>>>(w_qkv, x);                          // wqmean + xsum_part
    qmean_gate_kernel<<<144, 256>>>(x, ln_g, ln_b, w1, b1, w2, b2); // qmean+gate + xsum_reduce
    topk_vsum_kernel<<<1028, 256>>>(w_qkv);                       // topk + vsumall
    inact_row_kernel<<<DIM, 256>>>(w_out, b_out);                 // vsumall-style GEMV
    qkv_active_gemm_kernel<<<dim3(3 * INNER / 64, Bx * 2), 256>>>(x, w_qkv);
    attn_flash_kernel<<<544, 128>>>(out);                         // attn + bcast
    out_gemm_active_kernel<<<dim3(DIM / 64, Bx * 2), 256>>>(w_out, b_out, out);
}

// round 17
// speedup vs baseline: 1.9921x; 1.0321x over previous
#include <cuda_runtime.h>
#include <cuda_bf16.h>
#include <cstdint>

// Problem constants
#define Bx     4
#define Nn     1024
#define DIM    1024
#define HEADS  16
#define DH     64
#define INNER  1024
#define PROJ_H 16
#define TOP_K  256
#define SCALE  0.125f
#define LN_EPS 1e-5f

#define M_TOK  (Bx * Nn)          // 4096 tokens
#define BH     (Bx * HEADS)       // 64
#define GBK    16

// ---------------- scratch (device globals; no allocation allowed) -----------
__device__ float gWqm[DH * DIM];                 // (1/16) sum_h w_q rows
__device__ float gScores[Bx * Nn];
__device__ float gGate[Bx * Nn];
__device__ float gAttnOut[Bx * Nn * INNER];      // active rows only

__device__ int   gActIdx[Bx * TOP_K];
__device__ int   gActCount[Bx];
__device__ float gGateC[Bx * TOP_K];
__device__ float gQc[BH * TOP_K * DH];           // compact Q (active only)
__device__ float gKc[BH * TOP_K * DH];           // compact K
__device__ float gVc[BH * TOP_K * DH];           // compact V
__device__ float gXsumP[32 * Bx * DIM];          // partial x sums (32 slabs)
__device__ float gXsum[Bx * DIM];                // per-batch sum of x rows
__device__ float gVsumAll[BH * DH];              // = Wv . xsum
__device__ float gInactRow[Bx * DIM];

// ======== Kernel 1: prep = wqmean float4 (0..63) + xsum_part (64..575) ======
__global__ __launch_bounds__(256)
void prep_kernel(const float* __restrict__ Wqkv, const float* __restrict__ x)
{
    const int blk = blockIdx.x;
    const int tid = threadIdx.x;
    if (blk < 64) {
        const int f = blk * 256 + tid;           // float4 index, 0..16383
        const int d = f >> 8;                    // 0..63
        const int k4 = (f & 255) * 4;
        float4 s = make_float4(0.f, 0.f, 0.f, 0.f);
#pragma unroll
        for (int h = 0; h < HEADS; h++) {
            float4 v = *(const float4*)(Wqkv + (size_t)(h * DH + d) * DIM + k4);
            s.x += v.x; s.y += v.y; s.z += v.z; s.w += v.w;
        }
        s.x *= (1.0f / 16.0f); s.y *= (1.0f / 16.0f);
        s.z *= (1.0f / 16.0f); s.w *= (1.0f / 16.0f);
        *(float4*)(gWqm + (size_t)d * DIM + k4) = s;
    } else {
        const int e = blk - 64;                  // 0..511
        const int kb = e & 3, b = (e >> 2) & 3, sl = e >> 4;   // sl 0..31
        const int k = kb * 256 + tid;
        float s = 0.f;
        const float* p = x + ((size_t)b * Nn + sl * 32) * DIM + k;
#pragma unroll 8
        for (int n = 0; n < 32; n++) s += p[(size_t)n * DIM];
        gXsumP[((size_t)sl * Bx + b) * DIM + k] = s;
    }
}

// ==== Kernel 2: qmean GEMM + fused gate (0..127) + xsum_reduce (128..143) ===
__global__ __launch_bounds__(256)
void qmean_gate_kernel(const float* __restrict__ A,
                       const float* __restrict__ ln_g, const float* __restrict__ ln_b,
                       const float* __restrict__ w1, const float* __restrict__ b1,
                       const float* __restrict__ w2, const float* __restrict__ b2)
{
    const int blk = blockIdx.x;
    const int tid = threadIdx.x;

    if (blk >= 128) {                             // xsum_reduce
        const int e = blk - 128;                  // 0..15
        const int b = e >> 2;
        const int k = (e & 3) * 256 + tid;
        float s = 0.f;
#pragma unroll
        for (int sl = 0; sl < 32; sl++)
            s += gXsumP[((size_t)sl * Bx + b) * DIM + k];
        gXsum[b * DIM + k] = s;
        return;
    }

    __shared__ float As[GBK][32 + 4];
    __shared__ float Bs[GBK][64 + 4];
    __shared__ float Qs[32][65];

    const int m0 = blk * 32;
    const int lr = tid >> 2;
    const int lc = (tid & 3) * 4;
    const int ty = tid >> 4;
    const int tx = tid & 15;

    float acc[2][4];
#pragma unroll
    for (int i = 0; i < 2; i++)
#pragma unroll
        for (int j = 0; j < 4; j++) acc[i][j] = 0.f;

    for (int k0 = 0; k0 < DIM; k0 += GBK) {
        if (lr < 32) {
            float4 av = *(const float4*)(A + (size_t)(m0 + lr) * DIM + k0 + lc);
            As[lc + 0][lr] = av.x; As[lc + 1][lr] = av.y;
            As[lc + 2][lr] = av.z; As[lc + 3][lr] = av.w;
        }
        float4 bv = *(const float4*)(gWqm + (size_t)lr * DIM + k0 + lc);
        Bs[lc + 0][lr] = bv.x; Bs[lc + 1][lr] = bv.y;
        Bs[lc + 2][lr] = bv.z; Bs[lc + 3][lr] = bv.w;
        __syncthreads();
#pragma unroll
        for (int kk = 0; kk < GBK; kk++) {
            float2 a = *(const float2*)&As[kk][ty * 2];
            float4 b = *(const float4*)&Bs[kk][tx * 4];
            float br[4] = {b.x, b.y, b.z, b.w};
#pragma unroll
            for (int j = 0; j < 4; j++) {
                acc[0][j] += a.x * br[j];
                acc[1][j] += a.y * br[j];
            }
        }
        __syncthreads();
    }

#pragma unroll
    for (int i = 0; i < 2; i++)
#pragma unroll
        for (int j = 0; j < 4; j++)
            Qs[ty * 2 + i][tx * 4 + j] = acc[i][j];
    __syncthreads();

    if (tid < 32) {
        const int t = tid;
        float mu = 0.f, sq = 0.f;
#pragma unroll
        for (int e = 0; e < 64; e++) { float v = Qs[t][e]; mu += v; sq += v * v; }
        mu *= (1.0f / 64.0f);
        const float var = sq * (1.0f / 64.0f) - mu * mu;
        const float rs = rsqrtf(var + LN_EPS);
#pragma unroll
        for (int e = 0; e < 64; e++)
            Qs[t][e] = (Qs[t][e] - mu) * rs * ln_g[e] + ln_b[e];
        float sc = b2[0];
#pragma unroll
        for (int p = 0; p < PROJ_H; p++) {
            float a = b1[p];
#pragma unroll
            for (int e = 0; e < 64; e++) a += Qs[t][e] * w1[p * DH + e];
            float g = 0.5f * a * (1.0f + erff(a * 0.70710678118654752f));
            sc += g * w2[p];
        }
        gScores[m0 + t] = sc;
    }
}

// ===== Kernel 3: topk radix-select (0..3) + vsumall (blocks 4..1027) ========
__global__ __launch_bounds__(256)
void topk_vsum_kernel(const float* __restrict__ Wqkv)
{
    const int blk = blockIdx.x;
    const int tid = threadIdx.x;

    if (blk >= 4) {                               // vsumall: hd = blk-4
        const int hd = blk - 4;
        __shared__ float red[Bx][256];
        const float4* wrow = (const float4*)(Wqkv + (size_t)(2 * INNER + hd) * DIM);
        float4 w = wrow[tid];
#pragma unroll
        for (int b = 0; b < Bx; b++) {
            float4 v = ((const float4*)(gXsum + b * DIM))[tid];
            red[b][tid] = w.x * v.x + w.y * v.y + w.z * v.z + w.w * v.w;
        }
        __syncthreads();
        for (int off = 128; off > 0; off >>= 1) {
            if (tid < off)
#pragma unroll
                for (int b = 0; b < Bx; b++) red[b][tid] += red[b][tid + off];
            __syncthreads();
        }
        if (tid < Bx) gVsumAll[tid * 1024 + hd] = red[tid][0];
        return;
    }

    const int b = blk;
    __shared__ uint32_t keys[Nn];
    __shared__ uint32_t hist[256];
    __shared__ uint32_t sPrefix;
    __shared__ int sNeed, cnt;

    for (int t = tid; t < Nn; t += 256) {
        uint32_t u = __float_as_uint(gScores[b * Nn + t]);
        keys[t] = (u & 0x80000000u) ? ~u : (u | 0x80000000u);
    }
    if (tid == 0) { sPrefix = 0; sNeed = TOP_K; cnt = 0; }
    __syncthreads();

#pragma unroll
    for (int shift = 24; shift >= 0; shift -= 8) {
        hist[tid] = 0;
        __syncthreads();
        const uint32_t pref = sPrefix;
        for (int t = tid; t < Nn; t += 256) {
            uint32_t u = keys[t];
            bool match = (shift == 24) || ((u >> (shift + 8)) == pref);
            if (match) atomicAdd(&hist[(u >> shift) & 255u], 1u);
        }
        __syncthreads();
        if (tid == 0) {
            int acc = 0, k = sNeed;
            for (int bin = 255; bin >= 0; bin--) {
                int c = (int)hist[bin];
                if (acc + c >= k) {
                    sPrefix = (pref << 8) | (uint32_t)bin;
                    sNeed = k - acc;
                    break;
                }
                acc += c;
            }
        }
        __syncthreads();
    }

    const uint32_t Tu = sPrefix;
    const float thresh = (Tu & 0x80000000u) ? __uint_as_float(Tu & 0x7FFFFFFFu)
                                            : __uint_as_float(~Tu);

    for (int t = tid; t < Nn; t += 256) {
        float sc = gScores[b * Nn + t];
        float g = 0.0f;
        if (sc >= thresh) {
            int pos = atomicAdd(&cnt, 1);
            if (pos < TOP_K) {
                g = 1.0f / (1.0f + expf(-sc));
                gActIdx[b * TOP_K + pos] = t;
                gGateC[b * TOP_K + pos] = g;
            }
        }
        gGate[b * Nn + t] = g;
    }
    __syncthreads();
    if (tid == 0) gActCount[b] = (cnt < TOP_K) ? cnt : TOP_K;
}

// ---- Kernel 4: shared out-row per batch (vsumall-style, 1024 blocks) -------
__global__ __launch_bounds__(256)
void inact_row_kernel(const float* __restrict__ Bm, const float* __restrict__ bias)
{
    const int n = blockIdx.x;                    // 0..1023
    const int tid = threadIdx.x;
    __shared__ float red[Bx][256];

    const float4 w = ((const float4*)(Bm + (size_t)n * INNER))[tid];
#pragma unroll
    for (int b = 0; b < Bx; b++) {
        float4 v = ((const float4*)(gVsumAll + b * INNER))[tid];
        red[b][tid] = w.x * v.x + w.y * v.y + w.z * v.z + w.w * v.w;
    }
    __syncthreads();
    for (int off = 128; off > 0; off >>= 1) {
        if (tid < off)
#pragma unroll
            for (int b = 0; b < Bx; b++) red[b][tid] += red[b][tid + off];
        __syncthreads();
    }
    if (tid < Bx)
        gInactRow[tid * DIM + n] = red[tid][0] * (1.0f / (float)Nn) + bias[n];
}

// ---------------- Kernel 5: QKV projection (ACTIVE), double-buffered --------
__global__ __launch_bounds__(256)
void qkv_active_gemm_kernel(const float* __restrict__ A, const float* __restrict__ Wqkv)
{
    __shared__ float As[2][GBK][128 + 4];
    __shared__ float Bs[2][GBK][64 + 4];
    __shared__ int   sidx[128];
    __shared__ int   slive[128];

    const int tid = threadIdx.x;
    const int ty = tid >> 4;
    const int tx = tid & 15;
    const int b  = blockIdx.y >> 1;
    const int mt = blockIdx.y & 1;
    const int n0 = blockIdx.x * 64;

    const int alr = tid >> 1;
    const int alc = (tid & 1) * 8;
    const int blr = tid >> 2;
    const int blc = (tid & 3) * 4;

    const int cnt = gActCount[b];
    if (tid < 128) {
        const int ic = mt * 128 + tid;
        const bool lv = (ic < cnt);
        slive[tid] = lv;
        sidx[tid]  = lv ? gActIdx[b * TOP_K + ic] : gActIdx[b * TOP_K];
    }
    __syncthreads();

    const float* aptr = A + ((size_t)(b * Nn + sidx[alr])) * DIM + alc;
    const float* bptr = Wqkv + (size_t)(n0 + blr) * DIM + blc;

    float acc[8][4];
#pragma unroll
    for (int i = 0; i < 8; i++)
#pragma unroll
        for (int j = 0; j < 4; j++) acc[i][j] = 0.f;

    {
        float4 a0 = *(const float4*)(aptr);
        float4 a1 = *(const float4*)(aptr + 4);
        float4 bv = *(const float4*)(bptr);
#pragma unroll
        for (int i = 0; i < 4; i++) {
            As[0][alc + i][alr]     = ((const float*)&a0)[i];
            As[0][alc + 4 + i][alr] = ((const float*)&a1)[i];
            Bs[0][blc + i][blr]     = ((const float*)&bv)[i];
        }
    }
    __syncthreads();

    int buf = 0;
    for (int k0 = 0; k0 < DIM; k0 += GBK) {
        const bool nxt = (k0 + GBK) < DIM;
        float4 pa0, pa1, pbv;
        if (nxt) {
            pa0 = *(const float4*)(aptr + k0 + GBK);
            pa1 = *(const float4*)(aptr + k0 + GBK + 4);
            pbv = *(const float4*)(bptr + k0 + GBK);
        }
#pragma unroll
        for (int kk = 0; kk < GBK; kk++) {
            float4 x0 = *(const float4*)&As[buf][kk][ty * 8];
            float4 x1 = *(const float4*)&As[buf][kk][ty * 8 + 4];
            float4 y  = *(const float4*)&Bs[buf][kk][tx * 4];
            float xr[8] = {x0.x, x0.y, x0.z, x0.w, x1.x, x1.y, x1.z, x1.w};
            float yr[4] = {y.x, y.y, y.z, y.w};
#pragma unroll
            for (int i = 0; i < 8; i++)
#pragma unroll
                for (int j = 0; j < 4; j++) acc[i][j] += xr[i] * yr[j];
        }
        if (nxt) {
#pragma unroll
            for (int i = 0; i < 4; i++) {
                As[buf ^ 1][alc + i][alr]     = ((const float*)&pa0)[i];
                As[buf ^ 1][alc + 4 + i][alr] = ((const float*)&pa1)[i];
                Bs[buf ^ 1][blc + i][blr]     = ((const float*)&pbv)[i];
            }
            __syncthreads();
            buf ^= 1;
        }
    }

#pragma unroll
    for (int i = 0; i < 8; i++) {
        const int r = ty * 8 + i;
        if (slive[r]) {
            const int ic = mt * 128 + r;
#pragma unroll
            for (int j = 0; j < 4; j++) {
                const int n = n0 + tx * 4 + j;
                const int which = n >> 10;
                const int inner = n & 1023;
                const int h = inner >> 6, d = inner & 63;
                float* dst = (which == 0) ? gQc : (which == 1) ? gKc : gVc;
                dst[(((size_t)(b * HEADS + h)) * TOP_K + ic) * DH + d] = acc[i][j];
            }
        }
    }
}

// === Kernel 6: flash attention 64q x 64j (0..255) + inact bcast (256..287) ==
__global__ __launch_bounds__(256)
void attn_flash_kernel(float* __restrict__ C)
{
    const int blk = blockIdx.x;
    const int tid = threadIdx.x;

    if (blk >= 256) {                             // bcast: 128 tokens per block
        const int e = blk - 256;                  // 0..31
        for (int s = 0; s < 128; s++) {
            const int token = e * 128 + s;
            if (gGate[token] != 0.0f) continue;
            const int b = token >> 10;
            ((float4*)(C + (size_t)token * DIM))[tid] =
                ((const float4*)(gInactRow + b * DIM))[tid];
        }
        return;
    }

    const int bh = blk >> 2;        // 0..63
    const int qt = blk & 3;         // q-tile of 64
    const int b  = bh >> 4;
    const int h  = bh & 15;

    __shared__ float Qt[64][68];    // [d][q]   (transposed Q, 64 queries)
    __shared__ float KV[64][68];    // GEMM1: [d][j] (K^T); GEMM2: [j][d] (V)
    __shared__ float Ps[64][68];    // [q][j]  pm1
    __shared__ float lsm[64];
    __shared__ float gsm[64];

    const int cnt = gActCount[b];
    const int ty = tid >> 4;        // 0..15 -> q rows ty*4..+3
    const int tx = tid & 15;        // 0..15 -> j / d cols tx*4..+3

    // stage Q tile transposed: 64 q x 64 d (1024 float4, 4 per thread)
#pragma unroll
    for (int u = 0; u < 4; u++) {
        const int f = tid * 4 + u;
        const int q = f >> 4;
        const int c4 = (f & 15) * 4;
        float4 v = *(const float4*)(gQc + ((size_t)bh * TOP_K + qt * 64 + q) * DH + c4);
        Qt[c4 + 0][q] = v.x; Qt[c4 + 1][q] = v.y;
        Qt[c4 + 2][q] = v.z; Qt[c4 + 3][q] = v.w;
    }

    float giq[4];
#pragma unroll
    for (int i = 0; i < 4; i++) {
        const int ic = qt * 64 + ty * 4 + i;
        giq[i] = (ic < cnt) ? gGateC[b * TOP_K + ic] * SCALE : 0.f;
    }

    float acc[4][4];
#pragma unroll
    for (int i = 0; i < 4; i++)
#pragma unroll
        for (int j = 0; j < 4; j++) acc[i][j] = 0.f;
    float lacc[4] = {0.f, 0.f, 0.f, 0.f};

    for (int jt = 0; jt < 4; jt++) {
        const int j0 = jt * 64;
        __syncthreads();

        // stage K tile transposed [d][j] (1024 float4, 4 per thread)
#pragma unroll
        for (int u = 0; u < 4; u++) {
            const int f = tid * 4 + u;
            const int j = f >> 4;
            const int c4 = (f & 15) * 4;
            float4 v = *(const float4*)(gKc + ((size_t)bh * TOP_K + j0 + j) * DH + c4);
            KV[c4 + 0][j] = v.x; KV[c4 + 1][j] = v.y;
            KV[c4 + 2][j] = v.z; KV[c4 + 3][j] = v.w;
        }
        if (tid < 64)
            gsm[tid] = (j0 + tid < cnt) ? gGateC[b * TOP_K + j0 + tid] : 0.f;
        __syncthreads();

        // GEMM1: S[4q x 4j] = Q . K^T
        float s[4][4];
#pragma unroll
        for (int i = 0; i < 4; i++)
#pragma unroll
            for (int j = 0; j < 4; j++) s[i][j] = 0.f;
#pragma unroll 8
        for (int kk = 0; kk < 64; kk++) {
            float4 a = *(const float4*)&Qt[kk][ty * 4];
            float4 k4 = *(const float4*)&KV[kk][tx * 4];
            float ar[4] = {a.x, a.y, a.z, a.w};
            float kr[4] = {k4.x, k4.y, k4.z, k4.w};
#pragma unroll
            for (int i = 0; i < 4; i++)
#pragma unroll
                for (int j = 0; j < 4; j++) s[i][j] += ar[i] * kr[j];
        }

        float gjr[4];
#pragma unroll
        for (int j = 0; j < 4; j++) gjr[j] = gsm[tx * 4 + j];
        float rs[4];
#pragma unroll
        for (int i = 0; i < 4; i++) {
            float r = 0.f;
#pragma unroll
            for (int j = 0; j < 4; j++) {
                float p = __expf(s[i][j] * giq[i] * gjr[j]) - 1.0f;
                Ps[ty * 4 + i][tx * 4 + j] = p;
                r += p;
            }
            rs[i] = r;
        }
        // shuffle-reduce over the 16 tx lanes (warp halves have constant ty)
#pragma unroll
        for (int m = 8; m > 0; m >>= 1)
#pragma unroll
            for (int i = 0; i < 4; i++)
                rs[i] += __shfl_xor_sync(0xFFFFFFFFu, rs[i], m, 16);
        if (tx == 0)
#pragma unroll
            for (int i = 0; i < 4; i++) lacc[i] += rs[i];
        __syncthreads();

        // stage V [j][d] (1024 float4, 4 per thread)
#pragma unroll
        for (int u = 0; u < 4; u++) {
            const int f = tid * 4 + u;
            const int j = f >> 4;
            const int c4 = (f & 15) * 4;
            *(float4*)&KV[j][c4] =
                *(const float4*)(gVc + ((size_t)bh * TOP_K + j0 + j) * DH + c4);
        }
        __syncthreads();

        // GEMM2: acc[4q x 4d] += Ps . V
#pragma unroll 8
        for (int j = 0; j < 64; j++) {
            float ar[4];
#pragma unroll
            for (int i = 0; i < 4; i++) ar[i] = Ps[ty * 4 + i][j];
            float4 v4 = *(const float4*)&KV[j][tx * 4];
            float vr[4] = {v4.x, v4.y, v4.z, v4.w};
#pragma unroll
            for (int i = 0; i < 4; i++)
#pragma unroll
                for (int jj = 0; jj < 4; jj++) acc[i][jj] += ar[i] * vr[jj];
        }
    }

    if (tx == 0)
#pragma unroll
        for (int i = 0; i < 4; i++) lsm[ty * 4 + i] = lacc[i];
    __syncthreads();

    // epilogue: O = (acc + VsumAll) / (Nn + l)
#pragma unroll
    for (int i = 0; i < 4; i++) {
        const int q = ty * 4 + i;
        const int ic = qt * 64 + q;
        if (ic < cnt) {
            const int token = gActIdx[b * TOP_K + ic];
            const float inv = 1.0f / ((float)Nn + lsm[q]);
            float4 vall = *(const float4*)(gVsumAll + bh * DH + tx * 4);
            float4 o;
            o.x = (acc[i][0] + vall.x) * inv;
            o.y = (acc[i][1] + vall.y) * inv;
            o.z = (acc[i][2] + vall.z) * inv;
            o.w = (acc[i][3] + vall.w) * inv;
            *(float4*)(gAttnOut + (((size_t)(b * Nn + token)) * HEADS + h) * DH
                       + tx * 4) = o;
        }
    }
}

// ---------------- Kernel 7: output projection (ACTIVE), double-buffered -----
__global__ __launch_bounds__(256)
void out_gemm_active_kernel(const float* __restrict__ Bm, const float* __restrict__ bias,
                            float* __restrict__ C)
{
    __shared__ float As[2][GBK][128 + 4];
    __shared__ float Bs[2][GBK][64 + 4];
    __shared__ int   sidx[128];
    __shared__ int   slive[128];

    const int tid = threadIdx.x;
    const int ty = tid >> 4;
    const int tx = tid & 15;
    const int b  = blockIdx.y >> 1;
    const int mt = blockIdx.y & 1;
    const int n0 = blockIdx.x * 64;

    const int alr = tid >> 1;
    const int alc = (tid & 1) * 8;
    const int blr = tid >> 2;
    const int blc = (tid & 3) * 4;

    const int cnt = gActCount[b];
    if (tid < 128) {
        const int ic = mt * 128 + tid;
        const bool lv = (ic < cnt);
        slive[tid] = lv;
        sidx[tid]  = lv ? gActIdx[b * TOP_K + ic] : gActIdx[b * TOP_K];
    }
    __syncthreads();

    const float* aptr = gAttnOut + ((size_t)(b * Nn + sidx[alr])) * INNER + alc;
    const float* bptr = Bm + (size_t)(n0 + blr) * INNER + blc;

    float acc[8][4];
#pragma unroll
    for (int i = 0; i < 8; i++)
#pragma unroll
        for (int j = 0; j < 4; j++) acc[i][j] = 0.f;

    {
        float4 a0 = *(const float4*)(aptr);
        float4 a1 = *(const float4*)(aptr + 4);
        float4 bv = *(const float4*)(bptr);
#pragma unroll
        for (int i = 0; i < 4; i++) {
            As[0][alc + i][alr]     = ((const float*)&a0)[i];
            As[0][alc + 4 + i][alr] = ((const float*)&a1)[i];
            Bs[0][blc + i][blr]     = ((const float*)&bv)[i];
        }
    }
    __syncthreads();

    int buf = 0;
    for (int k0 = 0; k0 < INNER; k0 += GBK) {
        const bool nxt = (k0 + GBK) < INNER;
        float4 pa0, pa1, pbv;
        if (nxt) {
            pa0 = *(const float4*)(aptr + k0 + GBK);
            pa1 = *(const float4*)(aptr + k0 + GBK + 4);
            pbv = *(const float4*)(bptr + k0 + GBK);
        }
#pragma unroll
        for (int kk = 0; kk < GBK; kk++) {
            float4 x0 = *(const float4*)&As[buf][kk][ty * 8];
            float4 x1 = *(const float4*)&As[buf][kk][ty * 8 + 4];
            float4 y  = *(const float4*)&Bs[buf][kk][tx * 4];
            float xr[8] = {x0.x, x0.y, x0.z, x0.w, x1.x, x1.y, x1.z, x1.w};
            float yr[4] = {y.x, y.y, y.z, y.w};
#pragma unroll
            for (int i = 0; i < 8; i++)
#pragma unroll
                for (int j = 0; j < 4; j++) acc[i][j] += xr[i] * yr[j];
        }
        if (nxt) {
#pragma unroll
            for (int i = 0; i < 4; i++) {
                As[buf ^ 1][alc + i][alr]     = ((const float*)&pa0)[i];
                As[buf ^ 1][alc + 4 + i][alr] = ((const float*)&pa1)[i];
                Bs[buf ^ 1][blc + i][blr]     = ((const float*)&pbv)[i];
            }
            __syncthreads();
            buf ^= 1;
        }
    }

#pragma unroll
    for (int i = 0; i < 8; i++) {
        const int r = ty * 8 + i;
        if (slive[r]) {
            const int token = sidx[r];
#pragma unroll
            for (int j = 0; j < 4; j++) {
                const int n = n0 + tx * 4 + j;
                C[((size_t)(b * Nn + token)) * DIM + n] = acc[i][j] + bias[n];
            }
        }
    }
}

// ---------------- launch ----------------------------------------------------
extern "C" void kernel_launch(void* const* d_in, const int* in_sizes, int n_in,
                              void* d_out, int out_size)
{
    const float* x     = (const float*)d_in[0];
    const float* w_qkv = (const float*)d_in[1];
    const float* w_out = (const float*)d_in[2];
    const float* b_out = (const float*)d_in[3];
    const float* ln_g  = (const float*)d_in[4];
    const float* ln_b  = (const float*)d_in[5];
    const float* w1    = (const float*)d_in[6];
    const float* b1    = (const float*)d_in[7];
    const float* w2    = (const float*)d_in[8];
    const float* b2    = (const float*)d_in[9];
    float* out = (float*)d_out;

    prep_kernel<<<576, 256>>>(w_qkv, x);                          // wqmean + xsum_part
    qmean_gate_kernel<<<144, 256>>>(x, ln_g, ln_b, w1, b1, w2, b2); // qmean+gate + xsum_reduce
    topk_vsum_kernel<<<1028, 256>>>(w_qkv);                       // topk + vsumall
    inact_row_kernel<<<DIM, 256>>>(w_out, b_out);                 // vsumall-style GEMV
    qkv_active_gemm_kernel<<<dim3(3 * INNER / 64, Bx * 2), 256>>>(x, w_qkv);
    attn_flash_kernel<<<288, 256>>>(out);                         // attn 64x64 + bcast
    out_gemm_active_kernel<<<dim3(DIM / 64, Bx * 2), 256>>>(w_out, b_out, out);
}